// round 1
// baseline (speedup 1.0000x reference)
#include <cuda_runtime.h>
#include <math.h>

#define NN 100000
#define EE 1600000
#define ETOT (NN + EE)

// ---------------- scratch (static device globals; no runtime allocation) ----------------
__device__ float    g_deg[NN];
__device__ float    g_dinv[NN];
__device__ float    g_xt1[(size_t)NN * 128];
__device__ float    g_al1[NN * 4];
__device__ float    g_ar1[NN * 4];
__device__ unsigned g_max1[NN * 4];
__device__ float    g_sum1[NN * 4];
__device__ float    g_ex1[(size_t)ETOT * 4];
__device__ float    g_h1[(size_t)NN * 128];
__device__ float    g_xt2[NN * 16];
__device__ float    g_al2[NN];
__device__ float    g_ar2[NN];
__device__ unsigned g_max2[NN];
__device__ float    g_sum2[NN];
__device__ float    g_ex2[ETOT];

// ordered-uint encoding of float for atomicMax (monotonic for all finite floats)
__device__ __forceinline__ unsigned ford(float f) {
    int i = __float_as_int(f);
    return (i >= 0) ? (unsigned(i) | 0x80000000u) : unsigned(~i);
}
__device__ __forceinline__ float forddec(unsigned u) {
    int i = (u & 0x80000000u) ? int(u & 0x7fffffffu) : ~int(u);
    return __int_as_float(i);
}
__device__ __forceinline__ float lrelu(float a) { return a >= 0.f ? a : 0.2f * a; }

// ---------------- init ----------------
__global__ void k_init(float* __restrict__ out, int n) {
    int i = blockIdx.x * blockDim.x + threadIdx.x;
    if (i < n * 128) g_h1[i] = 0.f;
    if (i < n * 4) { g_sum1[i] = 0.f; g_max1[i] = 0u; }
    if (i < n)      { g_deg[i] = 1.0f; g_sum2[i] = 0.f; g_max2[i] = 0u; }
    if (i < n * 16) out[i] = 0.f;
}

__global__ void k_deg(const int* __restrict__ ei, int e) {
    int i = blockIdx.x * blockDim.x + threadIdx.x;
    if (i < e) atomicAdd(&g_deg[ei[i]], 1.0f);
}

__global__ void k_dinv(int n) {
    int i = blockIdx.x * blockDim.x + threadIdx.x;
    if (i < n) g_dinv[i] = rsqrtf(g_deg[i]);
}

// ---------------- GEMM1: xt1[n,128] = X[n,256] @ W1[256,128] ----------------
__global__ void k_gemm1(const float* __restrict__ X, const float* __restrict__ W, int n) {
    __shared__ float Xs[16][68];   // [k][m], padded for bank conflicts + 16B row align
    __shared__ float Ws[16][128];  // [k][n]
    int m0 = blockIdx.x * 64;
    int tid = threadIdx.x;
    int cg = tid & 31;   // 32 col-groups of 4
    int rg = tid >> 5;   // 8 row-groups of 8
    float acc[8][4];
#pragma unroll
    for (int i = 0; i < 8; i++)
#pragma unroll
        for (int j = 0; j < 4; j++) acc[i][j] = 0.f;

    for (int k0 = 0; k0 < 256; k0 += 16) {
        {
            int m = tid >> 2, kq = tid & 3;
            float4 v = make_float4(0.f, 0.f, 0.f, 0.f);
            if (m0 + m < n) v = *(const float4*)&X[(size_t)(m0 + m) * 256 + k0 + kq * 4];
            Xs[kq * 4 + 0][m] = v.x; Xs[kq * 4 + 1][m] = v.y;
            Xs[kq * 4 + 2][m] = v.z; Xs[kq * 4 + 3][m] = v.w;
        }
#pragma unroll
        for (int it = 0; it < 2; it++) {
            int task = tid + it * 256;
            int k = task >> 5, nq = task & 31;
            *(float4*)&Ws[k][nq * 4] = *(const float4*)&W[(size_t)(k0 + k) * 128 + nq * 4];
        }
        __syncthreads();
#pragma unroll
        for (int kk = 0; kk < 16; kk++) {
            float4 b4 = *(float4*)&Ws[kk][cg * 4];
            float4 a0 = *(float4*)&Xs[kk][rg * 8];
            float4 a1 = *(float4*)&Xs[kk][rg * 8 + 4];
            float a[8] = {a0.x, a0.y, a0.z, a0.w, a1.x, a1.y, a1.z, a1.w};
            float b[4] = {b4.x, b4.y, b4.z, b4.w};
#pragma unroll
            for (int i = 0; i < 8; i++)
#pragma unroll
                for (int j = 0; j < 4; j++) acc[i][j] += a[i] * b[j];
        }
        __syncthreads();
    }
#pragma unroll
    for (int i = 0; i < 8; i++) {
        int m = m0 + rg * 8 + i;
        if (m < n)
            *(float4*)&g_xt1[(size_t)m * 128 + cg * 4] =
                make_float4(acc[i][0], acc[i][1], acc[i][2], acc[i][3]);
    }
}

// ---------------- per-node attention projections layer1 ----------------
__global__ void k_alar1(const float* __restrict__ att, int n) {
    int t = blockIdx.x * blockDim.x + threadIdx.x;
    if (t >= n * 4) return;
    int node = t >> 2, h = t & 3;
    const float* xr = &g_xt1[(size_t)node * 128 + h * 32];
    float al = 0.f, ar = 0.f;
#pragma unroll
    for (int k = 0; k < 32; k += 4) {
        float4 v  = *(const float4*)&xr[k];
        float4 wl = *(const float4*)&att[h * 64 + k];
        float4 wr = *(const float4*)&att[h * 64 + 32 + k];
        al += v.x * wl.x + v.y * wl.y + v.z * wl.z + v.w * wl.w;
        ar += v.x * wr.x + v.y * wr.y + v.z * wr.z + v.w * wr.w;
    }
    g_al1[t] = al;
    g_ar1[t] = ar;
}

// ---------------- edge pass A1: segment max ----------------
__global__ void k_max1(const int* __restrict__ ei, int e, int n) {
    int t = blockIdx.x * blockDim.x + threadIdx.x;
    int et = e + n;
    if (t >= et) return;
    int r, c;
    if (t < e) { r = ei[t]; c = ei[e + t]; } else { r = c = t - e; }
    float4 ai = *(const float4*)&g_al1[c * 4];
    float4 aj = *(const float4*)&g_ar1[r * 4];
    atomicMax(&g_max1[c * 4 + 0], ford(lrelu(ai.x + aj.x)));
    atomicMax(&g_max1[c * 4 + 1], ford(lrelu(ai.y + aj.y)));
    atomicMax(&g_max1[c * 4 + 2], ford(lrelu(ai.z + aj.z)));
    atomicMax(&g_max1[c * 4 + 3], ford(lrelu(ai.w + aj.w)));
}

// ---------------- edge pass B1: exp + segment sum ----------------
__global__ void k_sum1(const int* __restrict__ ei, int e, int n) {
    int t = blockIdx.x * blockDim.x + threadIdx.x;
    int et = e + n;
    if (t >= et) return;
    int r, c;
    if (t < e) { r = ei[t]; c = ei[e + t]; } else { r = c = t - e; }
    float4 ai = *(const float4*)&g_al1[c * 4];
    float4 aj = *(const float4*)&g_ar1[r * 4];
    uint4 mu = *(const uint4*)&g_max1[c * 4];
    float ex0 = __expf(lrelu(ai.x + aj.x) - forddec(mu.x));
    float ex1 = __expf(lrelu(ai.y + aj.y) - forddec(mu.y));
    float ex2 = __expf(lrelu(ai.z + aj.z) - forddec(mu.z));
    float ex3 = __expf(lrelu(ai.w + aj.w) - forddec(mu.w));
    *(float4*)&g_ex1[(size_t)t * 4] = make_float4(ex0, ex1, ex2, ex3);
    atomicAdd(&g_sum1[c * 4 + 0], ex0);
    atomicAdd(&g_sum1[c * 4 + 1], ex1);
    atomicAdd(&g_sum1[c * 4 + 2], ex2);
    atomicAdd(&g_sum1[c * 4 + 3], ex3);
}

// ---------------- edge pass C1: weighted aggregation (warp per edge) ----------------
__global__ void k_agg1(const int* __restrict__ ei, int e, int n) {
    int eidx = blockIdx.x * 8 + (threadIdx.x >> 5);
    int q = threadIdx.x & 31;
    int et = e + n;
    if (eidx >= et) return;
    int r, c;
    if (eidx < e) { r = ei[eidx]; c = ei[e + eidx]; } else { r = c = eidx - e; }
    int h = q >> 3;
    float ew = g_dinv[r] * g_dinv[c];
    float ex = g_ex1[(size_t)eidx * 4 + h];
    float s  = g_sum1[c * 4 + h];
    float coef = ew * ex * __fdividef(1.0f, s + 1e-16f);
    float4 xj = *(const float4*)&g_xt1[(size_t)r * 128 + q * 4];
    float* dst = &g_h1[(size_t)c * 128 + q * 4];
    atomicAdd(dst + 0, coef * xj.x);
    atomicAdd(dst + 1, coef * xj.y);
    atomicAdd(dst + 2, coef * xj.z);
    atomicAdd(dst + 3, coef * xj.w);
}

__global__ void k_biasrelu1(const float* __restrict__ b1, int n) {
    int i = blockIdx.x * blockDim.x + threadIdx.x;
    if (i >= n * 128) return;
    float v = g_h1[i] + b1[i & 127];
    g_h1[i] = v > 0.f ? v : 0.f;
}

// ---------------- GEMM2: xt2[n,16] = h1[n,128] @ W2[128,16] ----------------
__global__ void k_gemm2(const float* __restrict__ W2, int n) {
    __shared__ float Hs[64][132];  // padded
    __shared__ float Ws[128 * 16];
    int m0 = blockIdx.x * 64;
    int tid = threadIdx.x;
#pragma unroll
    for (int it = 0; it < 8; it++) {
        int task = tid + it * 256;
        int row = task >> 5, q = task & 31;
        float4 v = make_float4(0.f, 0.f, 0.f, 0.f);
        if (m0 + row < n) v = *(const float4*)&g_h1[(size_t)(m0 + row) * 128 + q * 4];
        *(float4*)&Hs[row][q * 4] = v;
    }
#pragma unroll
    for (int it = 0; it < 2; it++) {
        int idx = tid + it * 256;
        ((float4*)Ws)[idx] = ((const float4*)W2)[idx];
    }
    __syncthreads();
    int row = tid >> 2, ng = tid & 3;
    float acc0 = 0.f, acc1 = 0.f, acc2 = 0.f, acc3 = 0.f;
#pragma unroll 8
    for (int k = 0; k < 128; k++) {
        float a = Hs[row][k];
        float4 b = *(float4*)&Ws[k * 16 + ng * 4];
        acc0 += a * b.x; acc1 += a * b.y; acc2 += a * b.z; acc3 += a * b.w;
    }
    int m = m0 + row;
    if (m < n) *(float4*)&g_xt2[(size_t)m * 16 + ng * 4] = make_float4(acc0, acc1, acc2, acc3);
}

__global__ void k_alar2(const float* __restrict__ att, int n) {
    int t = blockIdx.x * blockDim.x + threadIdx.x;
    if (t >= n) return;
    const float* xr = &g_xt2[(size_t)t * 16];
    float al = 0.f, ar = 0.f;
#pragma unroll
    for (int k = 0; k < 16; k += 4) {
        float4 v  = *(const float4*)&xr[k];
        float4 wl = *(const float4*)&att[k];
        float4 wr = *(const float4*)&att[16 + k];
        al += v.x * wl.x + v.y * wl.y + v.z * wl.z + v.w * wl.w;
        ar += v.x * wr.x + v.y * wr.y + v.z * wr.z + v.w * wr.w;
    }
    g_al2[t] = al;
    g_ar2[t] = ar;
}

__global__ void k_max2(const int* __restrict__ ei, int e, int n) {
    int t = blockIdx.x * blockDim.x + threadIdx.x;
    int et = e + n;
    if (t >= et) return;
    int r, c;
    if (t < e) { r = ei[t]; c = ei[e + t]; } else { r = c = t - e; }
    atomicMax(&g_max2[c], ford(lrelu(g_al2[c] + g_ar2[r])));
}

__global__ void k_sum2(const int* __restrict__ ei, int e, int n) {
    int t = blockIdx.x * blockDim.x + threadIdx.x;
    int et = e + n;
    if (t >= et) return;
    int r, c;
    if (t < e) { r = ei[t]; c = ei[e + t]; } else { r = c = t - e; }
    float a = lrelu(g_al2[c] + g_ar2[r]);
    float ex = __expf(a - forddec(g_max2[c]));
    g_ex2[t] = ex;
    atomicAdd(&g_sum2[c], ex);
}

__global__ void k_agg2(const int* __restrict__ ei, int e, int n, float* __restrict__ out) {
    int eidx = blockIdx.x * 64 + (threadIdx.x >> 2);
    int q = threadIdx.x & 3;
    int et = e + n;
    if (eidx >= et) return;
    int r, c;
    if (eidx < e) { r = ei[eidx]; c = ei[e + eidx]; } else { r = c = eidx - e; }
    float ew = g_dinv[r] * g_dinv[c];
    float coef = ew * g_ex2[eidx] * __fdividef(1.0f, g_sum2[c] + 1e-16f);
    float4 xj = *(const float4*)&g_xt2[(size_t)r * 16 + q * 4];
    float* dst = &out[(size_t)c * 16 + q * 4];
    atomicAdd(dst + 0, coef * xj.x);
    atomicAdd(dst + 1, coef * xj.y);
    atomicAdd(dst + 2, coef * xj.z);
    atomicAdd(dst + 3, coef * xj.w);
}

__global__ void k_bias2(const float* __restrict__ b2, int n, float* __restrict__ out) {
    int i = blockIdx.x * blockDim.x + threadIdx.x;
    if (i < n * 16) out[i] += b2[i & 15];
}

// ---------------- launch ----------------
extern "C" void kernel_launch(void* const* d_in, const int* in_sizes, int n_in,
                              void* d_out, int out_size) {
    const float* x    = (const float*)d_in[0];
    const int*   ei   = (const int*)d_in[1];
    const float* W1   = (const float*)d_in[2];
    const float* att1 = (const float*)d_in[3];
    const float* b1   = (const float*)d_in[4];
    const float* W2   = (const float*)d_in[5];
    const float* att2 = (const float*)d_in[6];
    const float* b2   = (const float*)d_in[7];
    float* out = (float*)d_out;

    int n = in_sizes[0] / 256;
    int e = in_sizes[1] / 2;
    int et = e + n;

    const int T = 256;
    k_init<<<(n * 128 + T - 1) / T, T>>>(out, n);
    k_deg<<<(e + T - 1) / T, T>>>(ei, e);
    k_dinv<<<(n + T - 1) / T, T>>>(n);

    k_gemm1<<<(n + 63) / 64, 256>>>(x, W1, n);
    k_alar1<<<(n * 4 + T - 1) / T, T>>>(att1, n);
    k_max1<<<(et + T - 1) / T, T>>>(ei, e, n);
    k_sum1<<<(et + T - 1) / T, T>>>(ei, e, n);
    k_agg1<<<(et + 7) / 8, 256>>>(ei, e, n);
    k_biasrelu1<<<(n * 128 + T - 1) / T, T>>>(b1, n);

    k_gemm2<<<(n + 63) / 64, 256>>>(W2, n);
    k_alar2<<<(n + T - 1) / T, T>>>(att2, n);
    k_max2<<<(et + T - 1) / T, T>>>(ei, e, n);
    k_sum2<<<(et + T - 1) / T, T>>>(ei, e, n);
    k_agg2<<<(et + 63) / 64, 256>>>(ei, e, n, out);
    k_bias2<<<(n * 16 + T - 1) / T, T>>>(b2, n, out);
}

// round 2
// speedup vs baseline: 1.6292x; 1.6292x over previous
#include <cuda_runtime.h>
#include <math.h>

#define NN 100000
#define EE 1600000
#define ETOT (NN + EE)

// ---------------- scratch (static device globals) ----------------
__device__ float    g_deg[NN];
__device__ float    g_dinv[NN];
__device__ float    g_xt1[(size_t)NN * 128];
__device__ float    g_al1[NN * 4];
__device__ float    g_ar1[NN * 4];
__device__ float    g_sum1[NN * 4];
__device__ float    g_ex1[(size_t)ETOT * 4];
__device__ float    g_h1[(size_t)NN * 128];
__device__ float    g_xt2[NN * 16];
__device__ float    g_al2[NN];
__device__ float    g_ar2[NN];
__device__ float    g_sum2[NN];
__device__ float    g_ex2[ETOT];
// CSR by destination (col)
__device__ int      g_cnt[NN];
__device__ int      g_off[NN + 1];
__device__ int      g_wpos[NN];
__device__ int2     g_adj[EE];     // (row, original edge id)

__device__ __forceinline__ float lrelu(float a) { return a >= 0.f ? a : 0.2f * a; }

// ---------------- init ----------------
__global__ void k_init(int n) {
    int i = blockIdx.x * blockDim.x + threadIdx.x;
    if (i < n * 4) g_sum1[i] = 0.f;
    if (i < n) { g_deg[i] = 1.0f; g_sum2[i] = 0.f; g_cnt[i] = 0; }
}

__global__ void k_deg_count(const int* __restrict__ ei, int e) {
    int i = blockIdx.x * blockDim.x + threadIdx.x;
    if (i < e) {
        atomicAdd(&g_deg[ei[i]], 1.0f);       // deg over row (source)
        atomicAdd(&g_cnt[ei[e + i]], 1);      // fan-in count over col (dest)
    }
}

__global__ void k_dinv(int n) {
    int i = blockIdx.x * blockDim.x + threadIdx.x;
    if (i < n) g_dinv[i] = rsqrtf(g_deg[i]);
}

// single-block scan: exclusive prefix over g_cnt -> g_off, g_wpos
__global__ void k_scan(int n) {
    __shared__ int s[1024];
    __shared__ int carry_s;
    if (threadIdx.x == 0) carry_s = 0;
    __syncthreads();
    for (int base = 0; base < n; base += 1024) {
        int cl = carry_s;
        int i = base + threadIdx.x;
        int v = (i < n) ? g_cnt[i] : 0;
        s[threadIdx.x] = v;
        __syncthreads();
#pragma unroll
        for (int d = 1; d < 1024; d <<= 1) {
            int t = (threadIdx.x >= d) ? s[threadIdx.x - d] : 0;
            __syncthreads();
            s[threadIdx.x] += t;
            __syncthreads();
        }
        int exc = s[threadIdx.x] - v + cl;
        if (i < n) { g_off[i] = exc; g_wpos[i] = exc; }
        __syncthreads();
        if (threadIdx.x == 1023) carry_s = cl + s[1023];
        __syncthreads();
    }
    if (threadIdx.x == 0) g_off[n] = carry_s;
}

__global__ void k_scatter(const int* __restrict__ ei, int e) {
    int i = blockIdx.x * blockDim.x + threadIdx.x;
    if (i >= e) return;
    int r = ei[i], c = ei[e + i];
    int p = atomicAdd(&g_wpos[c], 1);
    g_adj[p] = make_int2(r, i);
}

// ---------------- GEMM1: xt1[n,128] = X[n,256] @ W1[256,128] ----------------
__global__ void k_gemm1(const float* __restrict__ X, const float* __restrict__ W, int n) {
    __shared__ float Xs[16][68];
    __shared__ float Ws[16][128];
    int m0 = blockIdx.x * 64;
    int tid = threadIdx.x;
    int cg = tid & 31;
    int rg = tid >> 5;
    float acc[8][4];
#pragma unroll
    for (int i = 0; i < 8; i++)
#pragma unroll
        for (int j = 0; j < 4; j++) acc[i][j] = 0.f;

    for (int k0 = 0; k0 < 256; k0 += 16) {
        {
            int m = tid >> 2, kq = tid & 3;
            float4 v = make_float4(0.f, 0.f, 0.f, 0.f);
            if (m0 + m < n) v = *(const float4*)&X[(size_t)(m0 + m) * 256 + k0 + kq * 4];
            Xs[kq * 4 + 0][m] = v.x; Xs[kq * 4 + 1][m] = v.y;
            Xs[kq * 4 + 2][m] = v.z; Xs[kq * 4 + 3][m] = v.w;
        }
#pragma unroll
        for (int it = 0; it < 2; it++) {
            int task = tid + it * 256;
            int k = task >> 5, nq = task & 31;
            *(float4*)&Ws[k][nq * 4] = *(const float4*)&W[(size_t)(k0 + k) * 128 + nq * 4];
        }
        __syncthreads();
#pragma unroll
        for (int kk = 0; kk < 16; kk++) {
            float4 b4 = *(float4*)&Ws[kk][cg * 4];
            float4 a0 = *(float4*)&Xs[kk][rg * 8];
            float4 a1 = *(float4*)&Xs[kk][rg * 8 + 4];
            float a[8] = {a0.x, a0.y, a0.z, a0.w, a1.x, a1.y, a1.z, a1.w};
            float b[4] = {b4.x, b4.y, b4.z, b4.w};
#pragma unroll
            for (int i = 0; i < 8; i++)
#pragma unroll
                for (int j = 0; j < 4; j++) acc[i][j] += a[i] * b[j];
        }
        __syncthreads();
    }
#pragma unroll
    for (int i = 0; i < 8; i++) {
        int m = m0 + rg * 8 + i;
        if (m < n)
            *(float4*)&g_xt1[(size_t)m * 128 + cg * 4] =
                make_float4(acc[i][0], acc[i][1], acc[i][2], acc[i][3]);
    }
}

// ---------------- per-node attention projections layer1 ----------------
__global__ void k_alar1(const float* __restrict__ att, int n) {
    int t = blockIdx.x * blockDim.x + threadIdx.x;
    if (t >= n * 4) return;
    int node = t >> 2, h = t & 3;
    const float* xr = &g_xt1[(size_t)node * 128 + h * 32];
    float al = 0.f, ar = 0.f;
#pragma unroll
    for (int k = 0; k < 32; k += 4) {
        float4 v  = *(const float4*)&xr[k];
        float4 wl = *(const float4*)&att[h * 64 + k];
        float4 wr = *(const float4*)&att[h * 64 + 32 + k];
        al += v.x * wl.x + v.y * wl.y + v.z * wl.z + v.w * wl.w;
        ar += v.x * wr.x + v.y * wr.y + v.z * wr.z + v.w * wr.w;
    }
    g_al1[t] = al;
    g_ar1[t] = ar;
}

// ---------------- edge pass: exp + segment sum (no max shift; |alpha| small) ----------------
__global__ void k_sum1(const int* __restrict__ ei, int e, int n) {
    int t = blockIdx.x * blockDim.x + threadIdx.x;
    int et = e + n;
    if (t >= et) return;
    int r, c;
    if (t < e) { r = ei[t]; c = ei[e + t]; } else { r = c = t - e; }
    float4 ai = *(const float4*)&g_al1[c * 4];
    float4 aj = *(const float4*)&g_ar1[r * 4];
    float ex0 = __expf(lrelu(ai.x + aj.x));
    float ex1 = __expf(lrelu(ai.y + aj.y));
    float ex2 = __expf(lrelu(ai.z + aj.z));
    float ex3 = __expf(lrelu(ai.w + aj.w));
    *(float4*)&g_ex1[(size_t)t * 4] = make_float4(ex0, ex1, ex2, ex3);
    atomicAdd(&g_sum1[c * 4 + 0], ex0);
    atomicAdd(&g_sum1[c * 4 + 1], ex1);
    atomicAdd(&g_sum1[c * 4 + 2], ex2);
    atomicAdd(&g_sum1[c * 4 + 3], ex3);
}

// ---------------- CSR aggregation layer1: warp per node, no atomics, fused bias+relu ----------------
__global__ void k_agg1(const float* __restrict__ b1, int e, int n) {
    int w = (blockIdx.x * blockDim.x + threadIdx.x) >> 5;
    if (w >= n) return;
    int lane = threadIdx.x & 31;
    int h = lane >> 3;
    int c = w;
    float dc = g_dinv[c];
    float rs = __fdividef(1.0f, g_sum1[c * 4 + h] + 1e-16f);
    float4 acc;
    // self loop (edge id e + c)
    {
        float ex = g_ex1[(size_t)(e + c) * 4 + h];
        float coef = dc * dc * ex * rs;
        float4 xj = *(const float4*)&g_xt1[(size_t)c * 128 + lane * 4];
        acc.x = coef * xj.x; acc.y = coef * xj.y; acc.z = coef * xj.z; acc.w = coef * xj.w;
    }
    int beg = g_off[c], end = g_off[c + 1];
#pragma unroll 2
    for (int j = beg; j < end; j++) {
        int2 ad = g_adj[j];
        float ex = g_ex1[(size_t)ad.y * 4 + h];
        float coef = g_dinv[ad.x] * dc * ex * rs;
        float4 xj = *(const float4*)&g_xt1[(size_t)ad.x * 128 + lane * 4];
        acc.x += coef * xj.x; acc.y += coef * xj.y;
        acc.z += coef * xj.z; acc.w += coef * xj.w;
    }
    float4 b = *(const float4*)&b1[lane * 4];
    float4 o;
    o.x = fmaxf(acc.x + b.x, 0.f);
    o.y = fmaxf(acc.y + b.y, 0.f);
    o.z = fmaxf(acc.z + b.z, 0.f);
    o.w = fmaxf(acc.w + b.w, 0.f);
    *(float4*)&g_h1[(size_t)c * 128 + lane * 4] = o;
}

// ---------------- GEMM2: xt2[n,16] = h1[n,128] @ W2[128,16] ----------------
__global__ void k_gemm2(const float* __restrict__ W2, int n) {
    __shared__ float Hs[64][132];
    __shared__ float Ws[128 * 16];
    int m0 = blockIdx.x * 64;
    int tid = threadIdx.x;
#pragma unroll
    for (int it = 0; it < 8; it++) {
        int task = tid + it * 256;
        int row = task >> 5, q = task & 31;
        float4 v = make_float4(0.f, 0.f, 0.f, 0.f);
        if (m0 + row < n) v = *(const float4*)&g_h1[(size_t)(m0 + row) * 128 + q * 4];
        *(float4*)&Hs[row][q * 4] = v;
    }
#pragma unroll
    for (int it = 0; it < 2; it++) {
        int idx = tid + it * 256;
        ((float4*)Ws)[idx] = ((const float4*)W2)[idx];
    }
    __syncthreads();
    int row = tid >> 2, ng = tid & 3;
    float acc0 = 0.f, acc1 = 0.f, acc2 = 0.f, acc3 = 0.f;
#pragma unroll 8
    for (int k = 0; k < 128; k++) {
        float a = Hs[row][k];
        float4 b = *(float4*)&Ws[k * 16 + ng * 4];
        acc0 += a * b.x; acc1 += a * b.y; acc2 += a * b.z; acc3 += a * b.w;
    }
    int m = m0 + row;
    if (m < n) *(float4*)&g_xt2[(size_t)m * 16 + ng * 4] = make_float4(acc0, acc1, acc2, acc3);
}

__global__ void k_alar2(const float* __restrict__ att, int n) {
    int t = blockIdx.x * blockDim.x + threadIdx.x;
    if (t >= n) return;
    const float* xr = &g_xt2[(size_t)t * 16];
    float al = 0.f, ar = 0.f;
#pragma unroll
    for (int k = 0; k < 16; k += 4) {
        float4 v  = *(const float4*)&xr[k];
        float4 wl = *(const float4*)&att[k];
        float4 wr = *(const float4*)&att[16 + k];
        al += v.x * wl.x + v.y * wl.y + v.z * wl.z + v.w * wl.w;
        ar += v.x * wr.x + v.y * wr.y + v.z * wr.z + v.w * wr.w;
    }
    g_al2[t] = al;
    g_ar2[t] = ar;
}

__global__ void k_sum2(const int* __restrict__ ei, int e, int n) {
    int t = blockIdx.x * blockDim.x + threadIdx.x;
    int et = e + n;
    if (t >= et) return;
    int r, c;
    if (t < e) { r = ei[t]; c = ei[e + t]; } else { r = c = t - e; }
    float ex = __expf(lrelu(g_al2[c] + g_ar2[r]));
    g_ex2[t] = ex;
    atomicAdd(&g_sum2[c], ex);
}

// ---------------- CSR aggregation layer2: warp per node, fused bias ----------------
__global__ void k_agg2(const float* __restrict__ b2, int e, int n, float* __restrict__ out) {
    int w = (blockIdx.x * blockDim.x + threadIdx.x) >> 5;
    if (w >= n) return;
    int lane = threadIdx.x & 31;
    int ch = lane & 15;
    int c = w;
    float dc = g_dinv[c];
    float rs = __fdividef(1.0f, g_sum2[c] + 1e-16f);
    float acc;
    {
        float ex = g_ex2[e + c];
        float coef = dc * dc * ex * rs;
        acc = coef * g_xt2[(size_t)c * 16 + ch];
    }
    int beg = g_off[c], end = g_off[c + 1];
#pragma unroll 2
    for (int j = beg; j < end; j++) {
        int2 ad = g_adj[j];
        float ex = g_ex2[ad.y];
        float coef = g_dinv[ad.x] * dc * ex * rs;
        acc += coef * g_xt2[(size_t)ad.x * 16 + ch];
    }
    if (lane < 16) out[(size_t)c * 16 + ch] = acc + b2[ch];
}

// ---------------- launch ----------------
extern "C" void kernel_launch(void* const* d_in, const int* in_sizes, int n_in,
                              void* d_out, int out_size) {
    const float* x    = (const float*)d_in[0];
    const int*   ei   = (const int*)d_in[1];
    const float* W1   = (const float*)d_in[2];
    const float* att1 = (const float*)d_in[3];
    const float* b1   = (const float*)d_in[4];
    const float* W2   = (const float*)d_in[5];
    const float* att2 = (const float*)d_in[6];
    const float* b2   = (const float*)d_in[7];
    float* out = (float*)d_out;

    int n = in_sizes[0] / 256;
    int e = in_sizes[1] / 2;
    int et = e + n;

    const int T = 256;
    k_init<<<(n * 4 + T - 1) / T, T>>>(n);
    k_deg_count<<<(e + T - 1) / T, T>>>(ei, e);
    k_dinv<<<(n + T - 1) / T, T>>>(n);
    k_scan<<<1, 1024>>>(n);
    k_scatter<<<(e + T - 1) / T, T>>>(ei, e);

    k_gemm1<<<(n + 63) / 64, 256>>>(x, W1, n);
    k_alar1<<<(n * 4 + T - 1) / T, T>>>(att1, n);
    k_sum1<<<(et + T - 1) / T, T>>>(ei, e, n);
    k_agg1<<<(n * 32 + 255) / 256, 256>>>(b1, e, n);

    k_gemm2<<<(n + 63) / 64, 256>>>(W2, n);
    k_alar2<<<(n + T - 1) / T, T>>>(att2, n);
    k_sum2<<<(et + T - 1) / T, T>>>(ei, e, n);
    k_agg2<<<(n * 32 + 255) / 256, 256>>>(b2, e, n, out);
}

// round 3
// speedup vs baseline: 2.1029x; 1.2908x over previous
#include <cuda_runtime.h>
#include <math.h>

#define NN 100000
#define EE 1600000
#define ETOT (NN + EE)
#define NB_SCAN ((NN + 1023) / 1024)

// ---------------- scratch (static device globals) ----------------
__device__ float    g_deg[NN];
__device__ float    g_dinv[NN];
__device__ float    g_xt1[(size_t)NN * 128];
__device__ float    g_al1[NN * 4];
__device__ float    g_ar1[NN * 4];
__device__ float    g_sum1[NN * 4];
__device__ float    g_ex1[(size_t)ETOT * 4];
__device__ float    g_h1[(size_t)NN * 128];
__device__ float    g_xt2[NN * 16];
__device__ float    g_al2[NN];
__device__ float    g_ar2[NN];
__device__ float    g_sum2[NN];
__device__ float    g_ex2[ETOT];
// CSR by destination (col)
__device__ int      g_cnt[NN];
__device__ int      g_off[NN + 1];
__device__ int      g_wpos[NN];
__device__ int      g_bsum[NB_SCAN + 1];
__device__ int2     g_adj[EE];     // (row, original edge id)

__device__ __forceinline__ float lrelu(float a) { return a >= 0.f ? a : 0.2f * a; }

// ---------------- init ----------------
__global__ void k_init(int n) {
    int i = blockIdx.x * blockDim.x + threadIdx.x;
    if (i < n * 4) g_sum1[i] = 0.f;
    if (i < n) { g_deg[i] = 1.0f; g_sum2[i] = 0.f; g_cnt[i] = 0; }
}

__global__ void k_deg_count(const int* __restrict__ ei, int e) {
    int i = blockIdx.x * blockDim.x + threadIdx.x;
    if (i < e) {
        atomicAdd(&g_deg[ei[i]], 1.0f);       // deg over row (source)
        atomicAdd(&g_cnt[ei[e + i]], 1);      // fan-in count over col (dest)
    }
}

__global__ void k_dinv(int n) {
    int i = blockIdx.x * blockDim.x + threadIdx.x;
    if (i < n) g_dinv[i] = rsqrtf(g_deg[i]);
}

// ---------------- multi-block exclusive scan over g_cnt ----------------
// Phase 1: per-block scan (1024 threads), local exclusive in g_off, block total in g_bsum
__global__ void k_scan_blocks(int n) {
    __shared__ int warpsums[32];
    int i = blockIdx.x * 1024 + threadIdx.x;
    int lane = threadIdx.x & 31, wid = threadIdx.x >> 5;
    int v = (i < n) ? g_cnt[i] : 0;
    int s = v;
#pragma unroll
    for (int d = 1; d < 32; d <<= 1) {
        int t = __shfl_up_sync(0xffffffffu, s, d);
        if (lane >= d) s += t;
    }
    if (lane == 31) warpsums[wid] = s;
    __syncthreads();
    if (wid == 0) {
        int ws = warpsums[lane];
#pragma unroll
        for (int d = 1; d < 32; d <<= 1) {
            int t = __shfl_up_sync(0xffffffffu, ws, d);
            if (lane >= d) ws += t;
        }
        warpsums[lane] = ws;
    }
    __syncthreads();
    int base = (wid > 0) ? warpsums[wid - 1] : 0;
    int exc = s - v + base;
    if (i < n) g_off[i] = exc;
    if (threadIdx.x == 1023) g_bsum[blockIdx.x] = exc + v;
}

// Phase 2: single small block scans block totals (NB_SCAN <= 128) -> exclusive
__global__ void k_scan_tops(int nb) {
    __shared__ int warpsums[4];
    int lane = threadIdx.x & 31, wid = threadIdx.x >> 5;
    int v = (threadIdx.x < nb) ? g_bsum[threadIdx.x] : 0;
    int s = v;
#pragma unroll
    for (int d = 1; d < 32; d <<= 1) {
        int t = __shfl_up_sync(0xffffffffu, s, d);
        if (lane >= d) s += t;
    }
    if (lane == 31) warpsums[wid] = s;
    __syncthreads();
    int base = 0;
#pragma unroll
    for (int w = 0; w < 4; w++) if (w < wid) base += warpsums[w];
    if (threadIdx.x < nb) g_bsum[threadIdx.x] = s - v + base;  // exclusive
}

// Phase 3: add block offsets, finalize g_off / g_wpos
__global__ void k_scan_add(int n, int e) {
    int i = blockIdx.x * 1024 + threadIdx.x;
    if (i < n) {
        int o = g_off[i] + g_bsum[blockIdx.x];
        g_off[i] = o;
        g_wpos[i] = o;
    }
    if (i == 0) g_off[n] = e;
}

__global__ void k_scatter(const int* __restrict__ ei, int e) {
    int i = blockIdx.x * blockDim.x + threadIdx.x;
    if (i >= e) return;
    int r = ei[i], c = ei[e + i];
    int p = atomicAdd(&g_wpos[c], 1);
    g_adj[p] = make_int2(r, i);
}

// ---------------- GEMM1: xt1[n,128] = X[n,256] @ W1[256,128] ----------------
__global__ void k_gemm1(const float* __restrict__ X, const float* __restrict__ W, int n) {
    __shared__ float Xs[16][68];
    __shared__ float Ws[16][128];
    int m0 = blockIdx.x * 64;
    int tid = threadIdx.x;
    int cg = tid & 31;
    int rg = tid >> 5;
    float acc[8][4];
#pragma unroll
    for (int i = 0; i < 8; i++)
#pragma unroll
        for (int j = 0; j < 4; j++) acc[i][j] = 0.f;

    for (int k0 = 0; k0 < 256; k0 += 16) {
        {
            int m = tid >> 2, kq = tid & 3;
            float4 v = make_float4(0.f, 0.f, 0.f, 0.f);
            if (m0 + m < n) v = *(const float4*)&X[(size_t)(m0 + m) * 256 + k0 + kq * 4];
            Xs[kq * 4 + 0][m] = v.x; Xs[kq * 4 + 1][m] = v.y;
            Xs[kq * 4 + 2][m] = v.z; Xs[kq * 4 + 3][m] = v.w;
        }
#pragma unroll
        for (int it = 0; it < 2; it++) {
            int task = tid + it * 256;
            int k = task >> 5, nq = task & 31;
            *(float4*)&Ws[k][nq * 4] = *(const float4*)&W[(size_t)(k0 + k) * 128 + nq * 4];
        }
        __syncthreads();
#pragma unroll
        for (int kk = 0; kk < 16; kk++) {
            float4 b4 = *(float4*)&Ws[kk][cg * 4];
            float4 a0 = *(float4*)&Xs[kk][rg * 8];
            float4 a1 = *(float4*)&Xs[kk][rg * 8 + 4];
            float a[8] = {a0.x, a0.y, a0.z, a0.w, a1.x, a1.y, a1.z, a1.w};
            float b[4] = {b4.x, b4.y, b4.z, b4.w};
#pragma unroll
            for (int i = 0; i < 8; i++)
#pragma unroll
                for (int j = 0; j < 4; j++) acc[i][j] += a[i] * b[j];
        }
        __syncthreads();
    }
#pragma unroll
    for (int i = 0; i < 8; i++) {
        int m = m0 + rg * 8 + i;
        if (m < n)
            *(float4*)&g_xt1[(size_t)m * 128 + cg * 4] =
                make_float4(acc[i][0], acc[i][1], acc[i][2], acc[i][3]);
    }
}

// ---------------- per-node attention projections layer1 ----------------
__global__ void k_alar1(const float* __restrict__ att, int n) {
    int t = blockIdx.x * blockDim.x + threadIdx.x;
    if (t >= n * 4) return;
    int node = t >> 2, h = t & 3;
    const float* xr = &g_xt1[(size_t)node * 128 + h * 32];
    float al = 0.f, ar = 0.f;
#pragma unroll
    for (int k = 0; k < 32; k += 4) {
        float4 v  = *(const float4*)&xr[k];
        float4 wl = *(const float4*)&att[h * 64 + k];
        float4 wr = *(const float4*)&att[h * 64 + 32 + k];
        al += v.x * wl.x + v.y * wl.y + v.z * wl.z + v.w * wl.w;
        ar += v.x * wr.x + v.y * wr.y + v.z * wr.z + v.w * wr.w;
    }
    g_al1[t] = al;
    g_ar1[t] = ar;
}

// ---------------- edge pass: exp + segment sum (no max shift; |alpha| small) ----------------
__global__ void k_sum1(const int* __restrict__ ei, int e, int n) {
    int t = blockIdx.x * blockDim.x + threadIdx.x;
    int et = e + n;
    if (t >= et) return;
    int r, c;
    if (t < e) { r = ei[t]; c = ei[e + t]; } else { r = c = t - e; }
    float4 ai = *(const float4*)&g_al1[c * 4];
    float4 aj = *(const float4*)&g_ar1[r * 4];
    float ex0 = __expf(lrelu(ai.x + aj.x));
    float ex1 = __expf(lrelu(ai.y + aj.y));
    float ex2 = __expf(lrelu(ai.z + aj.z));
    float ex3 = __expf(lrelu(ai.w + aj.w));
    *(float4*)&g_ex1[(size_t)t * 4] = make_float4(ex0, ex1, ex2, ex3);
    atomicAdd(&g_sum1[c * 4 + 0], ex0);
    atomicAdd(&g_sum1[c * 4 + 1], ex1);
    atomicAdd(&g_sum1[c * 4 + 2], ex2);
    atomicAdd(&g_sum1[c * 4 + 3], ex3);
}

// ---------------- CSR aggregation layer1: warp per node, no atomics, fused bias+relu ----------------
__global__ void k_agg1(const float* __restrict__ b1, int e, int n) {
    int w = (blockIdx.x * blockDim.x + threadIdx.x) >> 5;
    if (w >= n) return;
    int lane = threadIdx.x & 31;
    int h = lane >> 3;
    int c = w;
    float dc = g_dinv[c];
    float rs = __fdividef(1.0f, g_sum1[c * 4 + h] + 1e-16f);
    float4 acc;
    // self loop (edge id e + c)
    {
        float ex = g_ex1[(size_t)(e + c) * 4 + h];
        float coef = dc * dc * ex * rs;
        float4 xj = *(const float4*)&g_xt1[(size_t)c * 128 + lane * 4];
        acc.x = coef * xj.x; acc.y = coef * xj.y; acc.z = coef * xj.z; acc.w = coef * xj.w;
    }
    int beg = g_off[c], end = g_off[c + 1];
#pragma unroll 2
    for (int j = beg; j < end; j++) {
        int2 ad = g_adj[j];
        float ex = g_ex1[(size_t)ad.y * 4 + h];
        float coef = g_dinv[ad.x] * dc * ex * rs;
        float4 xj = *(const float4*)&g_xt1[(size_t)ad.x * 128 + lane * 4];
        acc.x += coef * xj.x; acc.y += coef * xj.y;
        acc.z += coef * xj.z; acc.w += coef * xj.w;
    }
    float4 b = *(const float4*)&b1[lane * 4];
    float4 o;
    o.x = fmaxf(acc.x + b.x, 0.f);
    o.y = fmaxf(acc.y + b.y, 0.f);
    o.z = fmaxf(acc.z + b.z, 0.f);
    o.w = fmaxf(acc.w + b.w, 0.f);
    *(float4*)&g_h1[(size_t)c * 128 + lane * 4] = o;
}

// ---------------- GEMM2: xt2[n,16] = h1[n,128] @ W2[128,16] ----------------
__global__ void k_gemm2(const float* __restrict__ W2, int n) {
    __shared__ float Hs[64][132];
    __shared__ float Ws[128 * 16];
    int m0 = blockIdx.x * 64;
    int tid = threadIdx.x;
#pragma unroll
    for (int it = 0; it < 8; it++) {
        int task = tid + it * 256;
        int row = task >> 5, q = task & 31;
        float4 v = make_float4(0.f, 0.f, 0.f, 0.f);
        if (m0 + row < n) v = *(const float4*)&g_h1[(size_t)(m0 + row) * 128 + q * 4];
        *(float4*)&Hs[row][q * 4] = v;
    }
#pragma unroll
    for (int it = 0; it < 2; it++) {
        int idx = tid + it * 256;
        ((float4*)Ws)[idx] = ((const float4*)W2)[idx];
    }
    __syncthreads();
    int row = tid >> 2, ng = tid & 3;
    float acc0 = 0.f, acc1 = 0.f, acc2 = 0.f, acc3 = 0.f;
#pragma unroll 8
    for (int k = 0; k < 128; k++) {
        float a = Hs[row][k];
        float4 b = *(float4*)&Ws[k * 16 + ng * 4];
        acc0 += a * b.x; acc1 += a * b.y; acc2 += a * b.z; acc3 += a * b.w;
    }
    int m = m0 + row;
    if (m < n) *(float4*)&g_xt2[(size_t)m * 16 + ng * 4] = make_float4(acc0, acc1, acc2, acc3);
}

__global__ void k_alar2(const float* __restrict__ att, int n) {
    int t = blockIdx.x * blockDim.x + threadIdx.x;
    if (t >= n) return;
    const float* xr = &g_xt2[(size_t)t * 16];
    float al = 0.f, ar = 0.f;
#pragma unroll
    for (int k = 0; k < 16; k += 4) {
        float4 v  = *(const float4*)&xr[k];
        float4 wl = *(const float4*)&att[k];
        float4 wr = *(const float4*)&att[16 + k];
        al += v.x * wl.x + v.y * wl.y + v.z * wl.z + v.w * wl.w;
        ar += v.x * wr.x + v.y * wr.y + v.z * wr.z + v.w * wr.w;
    }
    g_al2[t] = al;
    g_ar2[t] = ar;
}

__global__ void k_sum2(const int* __restrict__ ei, int e, int n) {
    int t = blockIdx.x * blockDim.x + threadIdx.x;
    int et = e + n;
    if (t >= et) return;
    int r, c;
    if (t < e) { r = ei[t]; c = ei[e + t]; } else { r = c = t - e; }
    float ex = __expf(lrelu(g_al2[c] + g_ar2[r]));
    g_ex2[t] = ex;
    atomicAdd(&g_sum2[c], ex);
}

// ---------------- CSR aggregation layer2: warp per node, fused bias ----------------
__global__ void k_agg2(const float* __restrict__ b2, int e, int n, float* __restrict__ out) {
    int w = (blockIdx.x * blockDim.x + threadIdx.x) >> 5;
    if (w >= n) return;
    int lane = threadIdx.x & 31;
    int ch = lane & 15;
    int c = w;
    float dc = g_dinv[c];
    float rs = __fdividef(1.0f, g_sum2[c] + 1e-16f);
    float acc;
    {
        float ex = g_ex2[e + c];
        float coef = dc * dc * ex * rs;
        acc = coef * g_xt2[(size_t)c * 16 + ch];
    }
    int beg = g_off[c], end = g_off[c + 1];
#pragma unroll 2
    for (int j = beg; j < end; j++) {
        int2 ad = g_adj[j];
        float ex = g_ex2[ad.y];
        float coef = g_dinv[ad.x] * dc * ex * rs;
        acc += coef * g_xt2[(size_t)ad.x * 16 + ch];
    }
    if (lane < 16) out[(size_t)c * 16 + ch] = acc + b2[ch];
}

// ---------------- launch ----------------
extern "C" void kernel_launch(void* const* d_in, const int* in_sizes, int n_in,
                              void* d_out, int out_size) {
    const float* x    = (const float*)d_in[0];
    const int*   ei   = (const int*)d_in[1];
    const float* W1   = (const float*)d_in[2];
    const float* att1 = (const float*)d_in[3];
    const float* b1   = (const float*)d_in[4];
    const float* W2   = (const float*)d_in[5];
    const float* att2 = (const float*)d_in[6];
    const float* b2   = (const float*)d_in[7];
    float* out = (float*)d_out;

    int n = in_sizes[0] / 256;
    int e = in_sizes[1] / 2;
    int et = e + n;
    int nb = (n + 1023) / 1024;

    const int T = 256;
    k_init<<<(n * 4 + T - 1) / T, T>>>(n);
    k_deg_count<<<(e + T - 1) / T, T>>>(ei, e);
    k_dinv<<<(n + T - 1) / T, T>>>(n);
    k_scan_blocks<<<nb, 1024>>>(n);
    k_scan_tops<<<1, 128>>>(nb);
    k_scan_add<<<nb, 1024>>>(n, e);
    k_scatter<<<(e + T - 1) / T, T>>>(ei, e);

    k_gemm1<<<(n + 63) / 64, 256>>>(x, W1, n);
    k_alar1<<<(n * 4 + T - 1) / T, T>>>(att1, n);
    k_sum1<<<(et + T - 1) / T, T>>>(ei, e, n);
    k_agg1<<<(n * 32 + 255) / 256, 256>>>(b1, e, n);

    k_gemm2<<<(n + 63) / 64, 256>>>(W2, n);
    k_alar2<<<(n + T - 1) / T, T>>>(att2, n);
    k_sum2<<<(et + T - 1) / T, T>>>(ei, e, n);
    k_agg2<<<(n * 32 + 255) / 256, 256>>>(b2, e, n, out);
}

// round 4
// speedup vs baseline: 2.3284x; 1.1072x over previous
#include <cuda_runtime.h>
#include <math.h>
#include <stdint.h>

#define NN 100000
#define EE 1600000
#define ETOT (NN + EE)
#define NB_SCAN ((NN + 1023) / 1024)

// ---------------- scratch (static device globals) ----------------
__device__ float    g_deg[NN];
__device__ float    g_dinv[NN];
__device__ float    g_xt1[(size_t)NN * 128];
__device__ float    g_al1[NN * 4];
__device__ float    g_ar1[NN * 4];
__device__ float    g_sum1[NN * 4];
__device__ float    g_ex1[(size_t)ETOT * 4];
__device__ float    g_h1[(size_t)NN * 128];
__device__ float    g_xt2[NN * 16];
__device__ float    g_al2[NN];
__device__ float    g_ar2[NN];
__device__ float    g_sum2[NN];
__device__ float    g_ex2[ETOT];
// CSR by destination (col)
__device__ int      g_cnt[NN];
__device__ int      g_off[NN + 1];
__device__ int      g_wpos[NN];
__device__ int      g_bsum[NB_SCAN + 1];
__device__ int2     g_adj[EE];     // (row, original edge id)

__device__ __forceinline__ float lrelu(float a) { return a >= 0.f ? a : 0.2f * a; }

// float -> tf32 (round-to-nearest), bit pattern carried in a float container
__device__ __forceinline__ float f2tf(float f) {
    uint32_t u;
    asm("cvt.rna.tf32.f32 %0, %1;" : "=r"(u) : "f"(f));
    return __uint_as_float(u);
}

__device__ __forceinline__ void mma_tf32(float* c, const uint32_t* a, const uint32_t* b) {
    asm volatile(
        "mma.sync.aligned.m16n8k8.row.col.f32.tf32.tf32.f32 "
        "{%0,%1,%2,%3}, {%4,%5,%6,%7}, {%8,%9}, {%0,%1,%2,%3};"
        : "+f"(c[0]), "+f"(c[1]), "+f"(c[2]), "+f"(c[3])
        : "r"(a[0]), "r"(a[1]), "r"(a[2]), "r"(a[3]), "r"(b[0]), "r"(b[1]));
}

// ---------------- init ----------------
__global__ void k_init(int n) {
    int i = blockIdx.x * blockDim.x + threadIdx.x;
    if (i < n * 4) g_sum1[i] = 0.f;
    if (i < n) { g_deg[i] = 1.0f; g_sum2[i] = 0.f; g_cnt[i] = 0; }
}

__global__ void k_deg_count(const int* __restrict__ ei, int e) {
    int i = blockIdx.x * blockDim.x + threadIdx.x;
    if (i < e) {
        atomicAdd(&g_deg[ei[i]], 1.0f);
        atomicAdd(&g_cnt[ei[e + i]], 1);
    }
}

__global__ void k_dinv(int n) {
    int i = blockIdx.x * blockDim.x + threadIdx.x;
    if (i < n) g_dinv[i] = rsqrtf(g_deg[i]);
}

// ---------------- multi-block exclusive scan over g_cnt ----------------
__global__ void k_scan_blocks(int n) {
    __shared__ int warpsums[32];
    int i = blockIdx.x * 1024 + threadIdx.x;
    int lane = threadIdx.x & 31, wid = threadIdx.x >> 5;
    int v = (i < n) ? g_cnt[i] : 0;
    int s = v;
#pragma unroll
    for (int d = 1; d < 32; d <<= 1) {
        int t = __shfl_up_sync(0xffffffffu, s, d);
        if (lane >= d) s += t;
    }
    if (lane == 31) warpsums[wid] = s;
    __syncthreads();
    if (wid == 0) {
        int ws = warpsums[lane];
#pragma unroll
        for (int d = 1; d < 32; d <<= 1) {
            int t = __shfl_up_sync(0xffffffffu, ws, d);
            if (lane >= d) ws += t;
        }
        warpsums[lane] = ws;
    }
    __syncthreads();
    int base = (wid > 0) ? warpsums[wid - 1] : 0;
    int exc = s - v + base;
    if (i < n) g_off[i] = exc;
    if (threadIdx.x == 1023) g_bsum[blockIdx.x] = exc + v;
}

__global__ void k_scan_tops(int nb) {
    __shared__ int warpsums[4];
    int lane = threadIdx.x & 31, wid = threadIdx.x >> 5;
    int v = (threadIdx.x < nb) ? g_bsum[threadIdx.x] : 0;
    int s = v;
#pragma unroll
    for (int d = 1; d < 32; d <<= 1) {
        int t = __shfl_up_sync(0xffffffffu, s, d);
        if (lane >= d) s += t;
    }
    if (lane == 31) warpsums[wid] = s;
    __syncthreads();
    int base = 0;
#pragma unroll
    for (int w = 0; w < 4; w++) if (w < wid) base += warpsums[w];
    if (threadIdx.x < nb) g_bsum[threadIdx.x] = s - v + base;
}

__global__ void k_scan_add(int n, int e) {
    int i = blockIdx.x * 1024 + threadIdx.x;
    if (i < n) {
        int o = g_off[i] + g_bsum[blockIdx.x];
        g_off[i] = o;
        g_wpos[i] = o;
    }
    if (i == 0) g_off[n] = e;
}

__global__ void k_scatter(const int* __restrict__ ei, int e) {
    int i = blockIdx.x * blockDim.x + threadIdx.x;
    if (i >= e) return;
    int r = ei[i], c = ei[e + i];
    int p = atomicAdd(&g_wpos[c], 1);
    g_adj[p] = make_int2(r, i);
}

// ---------------- GEMM1 (tf32 tensor cores): xt1[n,128] = X[n,256] @ W1[256,128] ----------------
// Block tile 128x128, 8 warps in 2x4 (m x n), warp tile 64x32.
__global__ __launch_bounds__(256, 2) void k_gemm1(const float* __restrict__ X,
                                                  const float* __restrict__ W, int n) {
    __shared__ float Xs[16][132];  // [k][m], pad 4
    __shared__ float Ws[16][132];  // [k][n], pad 4
    int tid = threadIdx.x, lane = tid & 31, wid = tid >> 5;
    int m0 = blockIdx.x * 128;
    int wm = (wid & 1) * 64, wn = (wid >> 1) * 32;

    float acc[4][4][4];
#pragma unroll
    for (int mt = 0; mt < 4; mt++)
#pragma unroll
        for (int nt = 0; nt < 4; nt++)
#pragma unroll
            for (int q = 0; q < 4; q++) acc[mt][nt][q] = 0.f;

    int lm = tid & 127;             // X row within tile
    int lkq = (tid >> 7) * 8;       // k sub-offset: 0 or 8
    int wk = tid >> 4;              // W k row: 0..15
    int wq = (tid & 15) * 8;        // W col offset

    for (int k0 = 0; k0 < 256; k0 += 16) {
        float4 v0 = make_float4(0.f, 0.f, 0.f, 0.f), v1 = v0;
        if (m0 + lm < n) {
            const float* xp = &X[(size_t)(m0 + lm) * 256 + k0 + lkq];
            v0 = *(const float4*)xp;
            v1 = *(const float4*)(xp + 4);
        }
        Xs[lkq + 0][lm] = f2tf(v0.x); Xs[lkq + 1][lm] = f2tf(v0.y);
        Xs[lkq + 2][lm] = f2tf(v0.z); Xs[lkq + 3][lm] = f2tf(v0.w);
        Xs[lkq + 4][lm] = f2tf(v1.x); Xs[lkq + 5][lm] = f2tf(v1.y);
        Xs[lkq + 6][lm] = f2tf(v1.z); Xs[lkq + 7][lm] = f2tf(v1.w);

        const float* wp = &W[(size_t)(k0 + wk) * 128 + wq];
        float4 w0 = *(const float4*)wp;
        float4 w1 = *(const float4*)(wp + 4);
        Ws[wk][wq + 0] = f2tf(w0.x); Ws[wk][wq + 1] = f2tf(w0.y);
        Ws[wk][wq + 2] = f2tf(w0.z); Ws[wk][wq + 3] = f2tf(w0.w);
        Ws[wk][wq + 4] = f2tf(w1.x); Ws[wk][wq + 5] = f2tf(w1.y);
        Ws[wk][wq + 6] = f2tf(w1.z); Ws[wk][wq + 7] = f2tf(w1.w);
        __syncthreads();

#pragma unroll
        for (int kk = 0; kk < 16; kk += 8) {
            int ar = lane >> 2, ak = kk + (lane & 3);
            uint32_t a[4][4], b[4][2];
#pragma unroll
            for (int mt = 0; mt < 4; mt++) {
                int r = wm + mt * 16 + ar;
                a[mt][0] = __float_as_uint(Xs[ak][r]);
                a[mt][1] = __float_as_uint(Xs[ak][r + 8]);
                a[mt][2] = __float_as_uint(Xs[ak + 4][r]);
                a[mt][3] = __float_as_uint(Xs[ak + 4][r + 8]);
            }
#pragma unroll
            for (int nt = 0; nt < 4; nt++) {
                int c = wn + nt * 8 + ar;
                b[nt][0] = __float_as_uint(Ws[ak][c]);
                b[nt][1] = __float_as_uint(Ws[ak + 4][c]);
            }
#pragma unroll
            for (int mt = 0; mt < 4; mt++)
#pragma unroll
                for (int nt = 0; nt < 4; nt++)
                    mma_tf32(acc[mt][nt], a[mt], b[nt]);
        }
        __syncthreads();
    }

    int ar = lane >> 2, ac = (lane & 3) * 2;
#pragma unroll
    for (int mt = 0; mt < 4; mt++) {
        int r = m0 + wm + mt * 16 + ar;
#pragma unroll
        for (int nt = 0; nt < 4; nt++) {
            int c = wn + nt * 8 + ac;
            if (r < n)
                *(float2*)&g_xt1[(size_t)r * 128 + c] = make_float2(acc[mt][nt][0], acc[mt][nt][1]);
            if (r + 8 < n)
                *(float2*)&g_xt1[(size_t)(r + 8) * 128 + c] = make_float2(acc[mt][nt][2], acc[mt][nt][3]);
        }
    }
}

// ---------------- per-node attention projections layer1 ----------------
__global__ void k_alar1(const float* __restrict__ att, int n) {
    int t = blockIdx.x * blockDim.x + threadIdx.x;
    if (t >= n * 4) return;
    int node = t >> 2, h = t & 3;
    const float* xr = &g_xt1[(size_t)node * 128 + h * 32];
    float al = 0.f, ar = 0.f;
#pragma unroll
    for (int k = 0; k < 32; k += 4) {
        float4 v  = *(const float4*)&xr[k];
        float4 wl = *(const float4*)&att[h * 64 + k];
        float4 wr = *(const float4*)&att[h * 64 + 32 + k];
        al += v.x * wl.x + v.y * wl.y + v.z * wl.z + v.w * wl.w;
        ar += v.x * wr.x + v.y * wr.y + v.z * wr.z + v.w * wr.w;
    }
    g_al1[t] = al;
    g_ar1[t] = ar;
}

// ---------------- edge pass: exp + segment sum ----------------
__global__ void k_sum1(const int* __restrict__ ei, int e, int n) {
    int t = blockIdx.x * blockDim.x + threadIdx.x;
    int et = e + n;
    if (t >= et) return;
    int r, c;
    if (t < e) { r = ei[t]; c = ei[e + t]; } else { r = c = t - e; }
    float4 ai = *(const float4*)&g_al1[c * 4];
    float4 aj = *(const float4*)&g_ar1[r * 4];
    float ex0 = __expf(lrelu(ai.x + aj.x));
    float ex1 = __expf(lrelu(ai.y + aj.y));
    float ex2 = __expf(lrelu(ai.z + aj.z));
    float ex3 = __expf(lrelu(ai.w + aj.w));
    *(float4*)&g_ex1[(size_t)t * 4] = make_float4(ex0, ex1, ex2, ex3);
    atomicAdd(&g_sum1[c * 4 + 0], ex0);
    atomicAdd(&g_sum1[c * 4 + 1], ex1);
    atomicAdd(&g_sum1[c * 4 + 2], ex2);
    atomicAdd(&g_sum1[c * 4 + 3], ex3);
}

// ---------------- CSR aggregation layer1 ----------------
__global__ void k_agg1(const float* __restrict__ b1, int e, int n) {
    int w = (blockIdx.x * blockDim.x + threadIdx.x) >> 5;
    if (w >= n) return;
    int lane = threadIdx.x & 31;
    int h = lane >> 3;
    int c = w;
    float dc = g_dinv[c];
    float rs = __fdividef(1.0f, g_sum1[c * 4 + h] + 1e-16f);
    float4 acc;
    {
        float ex = g_ex1[(size_t)(e + c) * 4 + h];
        float coef = dc * dc * ex * rs;
        float4 xj = *(const float4*)&g_xt1[(size_t)c * 128 + lane * 4];
        acc.x = coef * xj.x; acc.y = coef * xj.y; acc.z = coef * xj.z; acc.w = coef * xj.w;
    }
    int beg = g_off[c], end = g_off[c + 1];
#pragma unroll 2
    for (int j = beg; j < end; j++) {
        int2 ad = g_adj[j];
        float ex = g_ex1[(size_t)ad.y * 4 + h];
        float coef = g_dinv[ad.x] * dc * ex * rs;
        float4 xj = *(const float4*)&g_xt1[(size_t)ad.x * 128 + lane * 4];
        acc.x += coef * xj.x; acc.y += coef * xj.y;
        acc.z += coef * xj.z; acc.w += coef * xj.w;
    }
    float4 b = *(const float4*)&b1[lane * 4];
    float4 o;
    o.x = fmaxf(acc.x + b.x, 0.f);
    o.y = fmaxf(acc.y + b.y, 0.f);
    o.z = fmaxf(acc.z + b.z, 0.f);
    o.w = fmaxf(acc.w + b.w, 0.f);
    *(float4*)&g_h1[(size_t)c * 128 + lane * 4] = o;
}

// ---------------- GEMM2 (tf32): xt2[n,16] = h1[n,128] @ W2[128,16] ----------------
// Block tile 128x16, 8 warps M-stacked, warp tile 16x16.
__global__ __launch_bounds__(256, 2) void k_gemm2(const float* __restrict__ W2, int n) {
    __shared__ float Hs[32][132];  // [k][m]
    __shared__ float Ws2[32][20];  // [k][n]
    int tid = threadIdx.x, lane = tid & 31, wid = tid >> 5;
    int m0 = blockIdx.x * 128;
    int wm = wid * 16;

    float acc[2][4];
#pragma unroll
    for (int nt = 0; nt < 2; nt++)
#pragma unroll
        for (int q = 0; q < 4; q++) acc[nt][q] = 0.f;

    int lm = tid & 127;
    int lkq = (tid >> 7) * 16;  // 0 or 16
    int wkk = tid >> 3, wc = (tid & 7) * 2;

    for (int k0 = 0; k0 < 128; k0 += 32) {
        float4 h[4];
        if (m0 + lm < n) {
            const float* hp = &g_h1[(size_t)(m0 + lm) * 128 + k0 + lkq];
#pragma unroll
            for (int j = 0; j < 4; j++) h[j] = *(const float4*)(hp + j * 4);
        } else {
#pragma unroll
            for (int j = 0; j < 4; j++) h[j] = make_float4(0.f, 0.f, 0.f, 0.f);
        }
#pragma unroll
        for (int j = 0; j < 4; j++) {
            Hs[lkq + j * 4 + 0][lm] = f2tf(h[j].x);
            Hs[lkq + j * 4 + 1][lm] = f2tf(h[j].y);
            Hs[lkq + j * 4 + 2][lm] = f2tf(h[j].z);
            Hs[lkq + j * 4 + 3][lm] = f2tf(h[j].w);
        }
        Ws2[wkk][wc]     = f2tf(W2[(size_t)(k0 + wkk) * 16 + wc]);
        Ws2[wkk][wc + 1] = f2tf(W2[(size_t)(k0 + wkk) * 16 + wc + 1]);
        __syncthreads();

#pragma unroll
        for (int kk = 0; kk < 32; kk += 8) {
            int ar = lane >> 2, ak = kk + (lane & 3);
            uint32_t a[4];
            a[0] = __float_as_uint(Hs[ak][wm + ar]);
            a[1] = __float_as_uint(Hs[ak][wm + ar + 8]);
            a[2] = __float_as_uint(Hs[ak + 4][wm + ar]);
            a[3] = __float_as_uint(Hs[ak + 4][wm + ar + 8]);
            uint32_t b0[2], b1[2];
            b0[0] = __float_as_uint(Ws2[ak][ar]);
            b0[1] = __float_as_uint(Ws2[ak + 4][ar]);
            b1[0] = __float_as_uint(Ws2[ak][8 + ar]);
            b1[1] = __float_as_uint(Ws2[ak + 4][8 + ar]);
            mma_tf32(acc[0], a, b0);
            mma_tf32(acc[1], a, b1);
        }
        __syncthreads();
    }

    int ar = lane >> 2, ac = (lane & 3) * 2;
#pragma unroll
    for (int nt = 0; nt < 2; nt++) {
        int r = m0 + wm + ar;
        int c = nt * 8 + ac;
        if (r < n)
            *(float2*)&g_xt2[(size_t)r * 16 + c] = make_float2(acc[nt][0], acc[nt][1]);
        if (r + 8 < n)
            *(float2*)&g_xt2[(size_t)(r + 8) * 16 + c] = make_float2(acc[nt][2], acc[nt][3]);
    }
}

__global__ void k_alar2(const float* __restrict__ att, int n) {
    int t = blockIdx.x * blockDim.x + threadIdx.x;
    if (t >= n) return;
    const float* xr = &g_xt2[(size_t)t * 16];
    float al = 0.f, ar = 0.f;
#pragma unroll
    for (int k = 0; k < 16; k += 4) {
        float4 v  = *(const float4*)&xr[k];
        float4 wl = *(const float4*)&att[k];
        float4 wr = *(const float4*)&att[16 + k];
        al += v.x * wl.x + v.y * wl.y + v.z * wl.z + v.w * wl.w;
        ar += v.x * wr.x + v.y * wr.y + v.z * wr.z + v.w * wr.w;
    }
    g_al2[t] = al;
    g_ar2[t] = ar;
}

__global__ void k_sum2(const int* __restrict__ ei, int e, int n) {
    int t = blockIdx.x * blockDim.x + threadIdx.x;
    int et = e + n;
    if (t >= et) return;
    int r, c;
    if (t < e) { r = ei[t]; c = ei[e + t]; } else { r = c = t - e; }
    float ex = __expf(lrelu(g_al2[c] + g_ar2[r]));
    g_ex2[t] = ex;
    atomicAdd(&g_sum2[c], ex);
}

__global__ void k_agg2(const float* __restrict__ b2, int e, int n, float* __restrict__ out) {
    int w = (blockIdx.x * blockDim.x + threadIdx.x) >> 5;
    if (w >= n) return;
    int lane = threadIdx.x & 31;
    int ch = lane & 15;
    int c = w;
    float dc = g_dinv[c];
    float rs = __fdividef(1.0f, g_sum2[c] + 1e-16f);
    float acc;
    {
        float ex = g_ex2[e + c];
        float coef = dc * dc * ex * rs;
        acc = coef * g_xt2[(size_t)c * 16 + ch];
    }
    int beg = g_off[c], end = g_off[c + 1];
#pragma unroll 2
    for (int j = beg; j < end; j++) {
        int2 ad = g_adj[j];
        float ex = g_ex2[ad.y];
        float coef = g_dinv[ad.x] * dc * ex * rs;
        acc += coef * g_xt2[(size_t)ad.x * 16 + ch];
    }
    if (lane < 16) out[(size_t)c * 16 + ch] = acc + b2[ch];
}

// ---------------- launch ----------------
extern "C" void kernel_launch(void* const* d_in, const int* in_sizes, int n_in,
                              void* d_out, int out_size) {
    const float* x    = (const float*)d_in[0];
    const int*   ei   = (const int*)d_in[1];
    const float* W1   = (const float*)d_in[2];
    const float* att1 = (const float*)d_in[3];
    const float* b1   = (const float*)d_in[4];
    const float* W2   = (const float*)d_in[5];
    const float* att2 = (const float*)d_in[6];
    const float* b2   = (const float*)d_in[7];
    float* out = (float*)d_out;

    int n = in_sizes[0] / 256;
    int e = in_sizes[1] / 2;
    int et = e + n;
    int nb = (n + 1023) / 1024;

    const int T = 256;
    k_init<<<(n * 4 + T - 1) / T, T>>>(n);
    k_deg_count<<<(e + T - 1) / T, T>>>(ei, e);
    k_dinv<<<(n + T - 1) / T, T>>>(n);
    k_scan_blocks<<<nb, 1024>>>(n);
    k_scan_tops<<<1, 128>>>(nb);
    k_scan_add<<<nb, 1024>>>(n, e);
    k_scatter<<<(e + T - 1) / T, T>>>(ei, e);

    k_gemm1<<<(n + 127) / 128, 256>>>(x, W1, n);
    k_alar1<<<(n * 4 + T - 1) / T, T>>>(att1, n);
    k_sum1<<<(et + T - 1) / T, T>>>(ei, e, n);
    k_agg1<<<(n * 32 + 255) / 256, 256>>>(b1, e, n);

    k_gemm2<<<(n + 127) / 128, 256>>>(W2, n);
    k_alar2<<<(n + T - 1) / T, T>>>(att2, n);
    k_sum2<<<(et + T - 1) / T, T>>>(ei, e, n);
    k_agg2<<<(n * 32 + 255) / 256, 256>>>(b2, e, n, out);
}

// round 5
// speedup vs baseline: 2.7508x; 1.1814x over previous
#include <cuda_runtime.h>
#include <math.h>
#include <stdint.h>

#define NN 100000
#define EE 1600000
#define NB_SCAN ((NN + 1023) / 1024)

// ---------------- scratch (static device globals) ----------------
__device__ float    g_deg[NN];
__device__ float    g_dinv[NN];
__device__ float    g_xt1[(size_t)NN * 128];
__device__ float    g_al1[NN * 4];
__device__ float    g_ar1[NN * 4];
__device__ float    g_h1[(size_t)NN * 128];
__device__ float    g_xt2[NN * 16];
__device__ float    g_al2[NN];
__device__ float    g_ar2[NN];
// CSR by destination (col)
__device__ int      g_cnt[NN];
__device__ int      g_off[NN + 1];
__device__ int      g_wpos[NN];
__device__ int      g_bsum[NB_SCAN + 1];
__device__ int      g_adj[EE];     // source row only

__device__ __forceinline__ float lrelu(float a) { return a >= 0.f ? a : 0.2f * a; }

// float -> tf32 (round-to-nearest)
__device__ __forceinline__ float f2tf(float f) {
    uint32_t u;
    asm("cvt.rna.tf32.f32 %0, %1;" : "=r"(u) : "f"(f));
    return __uint_as_float(u);
}

__device__ __forceinline__ void mma_tf32(float* c, const uint32_t* a, const uint32_t* b) {
    asm volatile(
        "mma.sync.aligned.m16n8k8.row.col.f32.tf32.tf32.f32 "
        "{%0,%1,%2,%3}, {%4,%5,%6,%7}, {%8,%9}, {%0,%1,%2,%3};"
        : "+f"(c[0]), "+f"(c[1]), "+f"(c[2]), "+f"(c[3])
        : "r"(a[0]), "r"(a[1]), "r"(a[2]), "r"(a[3]), "r"(b[0]), "r"(b[1]));
}

// ---------------- init ----------------
__global__ void k_init(int n) {
    int i = blockIdx.x * blockDim.x + threadIdx.x;
    if (i < n) { g_deg[i] = 1.0f; g_cnt[i] = 0; }
}

__global__ void k_deg_count(const int* __restrict__ ei, int e) {
    int i = blockIdx.x * blockDim.x + threadIdx.x;
    if (i < e) {
        atomicAdd(&g_deg[ei[i]], 1.0f);
        atomicAdd(&g_cnt[ei[e + i]], 1);
    }
}

__global__ void k_dinv(int n) {
    int i = blockIdx.x * blockDim.x + threadIdx.x;
    if (i < n) g_dinv[i] = rsqrtf(g_deg[i]);
}

// ---------------- multi-block exclusive scan over g_cnt ----------------
__global__ void k_scan_blocks(int n) {
    __shared__ int warpsums[32];
    int i = blockIdx.x * 1024 + threadIdx.x;
    int lane = threadIdx.x & 31, wid = threadIdx.x >> 5;
    int v = (i < n) ? g_cnt[i] : 0;
    int s = v;
#pragma unroll
    for (int d = 1; d < 32; d <<= 1) {
        int t = __shfl_up_sync(0xffffffffu, s, d);
        if (lane >= d) s += t;
    }
    if (lane == 31) warpsums[wid] = s;
    __syncthreads();
    if (wid == 0) {
        int ws = warpsums[lane];
#pragma unroll
        for (int d = 1; d < 32; d <<= 1) {
            int t = __shfl_up_sync(0xffffffffu, ws, d);
            if (lane >= d) ws += t;
        }
        warpsums[lane] = ws;
    }
    __syncthreads();
    int base = (wid > 0) ? warpsums[wid - 1] : 0;
    int exc = s - v + base;
    if (i < n) g_off[i] = exc;
    if (threadIdx.x == 1023) g_bsum[blockIdx.x] = exc + v;
}

__global__ void k_scan_tops(int nb) {
    __shared__ int warpsums[4];
    int lane = threadIdx.x & 31, wid = threadIdx.x >> 5;
    int v = (threadIdx.x < nb) ? g_bsum[threadIdx.x] : 0;
    int s = v;
#pragma unroll
    for (int d = 1; d < 32; d <<= 1) {
        int t = __shfl_up_sync(0xffffffffu, s, d);
        if (lane >= d) s += t;
    }
    if (lane == 31) warpsums[wid] = s;
    __syncthreads();
    int base = 0;
#pragma unroll
    for (int w = 0; w < 4; w++) if (w < wid) base += warpsums[w];
    if (threadIdx.x < nb) g_bsum[threadIdx.x] = s - v + base;
}

__global__ void k_scan_add(int n, int e) {
    int i = blockIdx.x * 1024 + threadIdx.x;
    if (i < n) {
        int o = g_off[i] + g_bsum[blockIdx.x];
        g_off[i] = o;
        g_wpos[i] = o;
    }
    if (i == 0) g_off[n] = e;
}

__global__ void k_scatter(const int* __restrict__ ei, int e) {
    int i = blockIdx.x * blockDim.x + threadIdx.x;
    if (i >= e) return;
    int r = ei[i], c = ei[e + i];
    int p = atomicAdd(&g_wpos[c], 1);
    g_adj[p] = r;
}

// ---------------- GEMM1 (tf32, reg-prefetch): xt1[n,128] = X[n,256] @ W1[256,128] ----------------
__global__ __launch_bounds__(256, 2) void k_gemm1(const float* __restrict__ X,
                                                  const float* __restrict__ W, int n) {
    __shared__ float Xs[16][132];
    __shared__ float Ws[16][132];
    int tid = threadIdx.x, lane = tid & 31, wid = tid >> 5;
    int m0 = blockIdx.x * 128;
    int wm = (wid & 1) * 64, wn = (wid >> 1) * 32;

    float acc[4][4][4];
#pragma unroll
    for (int mt = 0; mt < 4; mt++)
#pragma unroll
        for (int nt = 0; nt < 4; nt++)
#pragma unroll
            for (int q = 0; q < 4; q++) acc[mt][nt][q] = 0.f;

    int lm = tid & 127;
    int lkq = (tid >> 7) * 8;
    int wk = tid >> 4;
    int wq = (tid & 15) * 8;

    bool mok = (m0 + lm < n);
    const float* xbase = &X[(size_t)(m0 + lm) * 256 + lkq];
    const float* wbase = &W[(size_t)wk * 128 + wq];

    // preload tile 0
    float4 v0 = make_float4(0.f, 0.f, 0.f, 0.f), v1 = v0;
    if (mok) { v0 = *(const float4*)xbase; v1 = *(const float4*)(xbase + 4); }
    float4 w0 = *(const float4*)wbase;
    float4 w1 = *(const float4*)(wbase + 4);

    for (int k0 = 0; k0 < 256; k0 += 16) {
        Xs[lkq + 0][lm] = f2tf(v0.x); Xs[lkq + 1][lm] = f2tf(v0.y);
        Xs[lkq + 2][lm] = f2tf(v0.z); Xs[lkq + 3][lm] = f2tf(v0.w);
        Xs[lkq + 4][lm] = f2tf(v1.x); Xs[lkq + 5][lm] = f2tf(v1.y);
        Xs[lkq + 6][lm] = f2tf(v1.z); Xs[lkq + 7][lm] = f2tf(v1.w);
        Ws[wk][wq + 0] = f2tf(w0.x); Ws[wk][wq + 1] = f2tf(w0.y);
        Ws[wk][wq + 2] = f2tf(w0.z); Ws[wk][wq + 3] = f2tf(w0.w);
        Ws[wk][wq + 4] = f2tf(w1.x); Ws[wk][wq + 5] = f2tf(w1.y);
        Ws[wk][wq + 6] = f2tf(w1.z); Ws[wk][wq + 7] = f2tf(w1.w);
        __syncthreads();

        // prefetch next tile while MMAs run
        if (k0 + 16 < 256) {
            const float* xp = xbase + k0 + 16;
            const float* wp = wbase + (size_t)(k0 + 16) * 128;
            if (mok) { v0 = *(const float4*)xp; v1 = *(const float4*)(xp + 4); }
            w0 = *(const float4*)wp;
            w1 = *(const float4*)(wp + 4);
        }

#pragma unroll
        for (int kk = 0; kk < 16; kk += 8) {
            int ar = lane >> 2, ak = kk + (lane & 3);
            uint32_t a[4][4], b[4][2];
#pragma unroll
            for (int mt = 0; mt < 4; mt++) {
                int r = wm + mt * 16 + ar;
                a[mt][0] = __float_as_uint(Xs[ak][r]);
                a[mt][1] = __float_as_uint(Xs[ak][r + 8]);
                a[mt][2] = __float_as_uint(Xs[ak + 4][r]);
                a[mt][3] = __float_as_uint(Xs[ak + 4][r + 8]);
            }
#pragma unroll
            for (int nt = 0; nt < 4; nt++) {
                int c = wn + nt * 8 + ar;
                b[nt][0] = __float_as_uint(Ws[ak][c]);
                b[nt][1] = __float_as_uint(Ws[ak + 4][c]);
            }
#pragma unroll
            for (int mt = 0; mt < 4; mt++)
#pragma unroll
                for (int nt = 0; nt < 4; nt++)
                    mma_tf32(acc[mt][nt], a[mt], b[nt]);
        }
        __syncthreads();
    }

    int ar = lane >> 2, ac = (lane & 3) * 2;
#pragma unroll
    for (int mt = 0; mt < 4; mt++) {
        int r = m0 + wm + mt * 16 + ar;
#pragma unroll
        for (int nt = 0; nt < 4; nt++) {
            int c = wn + nt * 8 + ac;
            if (r < n)
                *(float2*)&g_xt1[(size_t)r * 128 + c] = make_float2(acc[mt][nt][0], acc[mt][nt][1]);
            if (r + 8 < n)
                *(float2*)&g_xt1[(size_t)(r + 8) * 128 + c] = make_float2(acc[mt][nt][2], acc[mt][nt][3]);
        }
    }
}

// ---------------- per-node attention projections layer1 ----------------
__global__ void k_alar1(const float* __restrict__ att, int n) {
    int t = blockIdx.x * blockDim.x + threadIdx.x;
    if (t >= n * 4) return;
    int node = t >> 2, h = t & 3;
    const float* xr = &g_xt1[(size_t)node * 128 + h * 32];
    float al = 0.f, ar = 0.f;
#pragma unroll
    for (int k = 0; k < 32; k += 4) {
        float4 v  = *(const float4*)&xr[k];
        float4 wl = *(const float4*)&att[h * 64 + k];
        float4 wr = *(const float4*)&att[h * 64 + 32 + k];
        al += v.x * wl.x + v.y * wl.y + v.z * wl.z + v.w * wl.w;
        ar += v.x * wr.x + v.y * wr.y + v.z * wr.z + v.w * wr.w;
    }
    g_al1[t] = al;
    g_ar1[t] = ar;
}

// ---------------- fused softmax + aggregation layer1 (warp per node) ----------------
__global__ void k_agg1(const float* __restrict__ b1, int n) {
    int w = (blockIdx.x * blockDim.x + threadIdx.x) >> 5;
    if (w >= n) return;
    int lane = threadIdx.x & 31;
    int c = w;
    float dc = g_dinv[c];
    float4 alc = *(const float4*)&g_al1[c * 4];
    float4 arc = *(const float4*)&g_ar1[c * 4];
    int beg = g_off[c], end = g_off[c + 1];

    // pass 1: softmax denominator per head
    float4 ps = make_float4(0.f, 0.f, 0.f, 0.f);
    for (int j = beg + lane; j < end; j += 32) {
        int r = __ldg(&g_adj[j]);
        float4 ar4 = *(const float4*)&g_ar1[r * 4];
        ps.x += __expf(lrelu(alc.x + ar4.x));
        ps.y += __expf(lrelu(alc.y + ar4.y));
        ps.z += __expf(lrelu(alc.z + ar4.z));
        ps.w += __expf(lrelu(alc.w + ar4.w));
    }
#pragma unroll
    for (int d = 16; d > 0; d >>= 1) {
        ps.x += __shfl_xor_sync(0xffffffffu, ps.x, d);
        ps.y += __shfl_xor_sync(0xffffffffu, ps.y, d);
        ps.z += __shfl_xor_sync(0xffffffffu, ps.z, d);
        ps.w += __shfl_xor_sync(0xffffffffu, ps.w, d);
    }
    float se0 = __expf(lrelu(alc.x + arc.x));
    float se1 = __expf(lrelu(alc.y + arc.y));
    float se2 = __expf(lrelu(alc.z + arc.z));
    float se3 = __expf(lrelu(alc.w + arc.w));
    float4 rs4;
    rs4.x = __fdividef(1.0f, ps.x + se0 + 1e-16f);
    rs4.y = __fdividef(1.0f, ps.y + se1 + 1e-16f);
    rs4.z = __fdividef(1.0f, ps.z + se2 + 1e-16f);
    rs4.w = __fdividef(1.0f, ps.w + se3 + 1e-16f);

    // pass 2: weighted gather-accumulate (lane -> 4 channels, head = lane>>3)
    int h = lane >> 3;
    float alh = h < 2 ? (h == 0 ? alc.x : alc.y) : (h == 2 ? alc.z : alc.w);
    float rsh = h < 2 ? (h == 0 ? rs4.x : rs4.y) : (h == 2 ? rs4.z : rs4.w);
    float seh = h < 2 ? (h == 0 ? se0 : se1) : (h == 2 ? se2 : se3);

    float4 acc;
    {
        float coef = dc * dc * seh * rsh;
        float4 xj = *(const float4*)&g_xt1[(size_t)c * 128 + lane * 4];
        acc.x = coef * xj.x; acc.y = coef * xj.y; acc.z = coef * xj.z; acc.w = coef * xj.w;
    }
#pragma unroll 2
    for (int j = beg; j < end; j++) {
        int r = __ldg(&g_adj[j]);
        float arh = g_ar1[r * 4 + h];
        float ex = __expf(lrelu(alh + arh));
        float coef = g_dinv[r] * dc * ex * rsh;
        float4 xj = *(const float4*)&g_xt1[(size_t)r * 128 + lane * 4];
        acc.x += coef * xj.x; acc.y += coef * xj.y;
        acc.z += coef * xj.z; acc.w += coef * xj.w;
    }
    float4 b = *(const float4*)&b1[lane * 4];
    float4 o;
    o.x = fmaxf(acc.x + b.x, 0.f);
    o.y = fmaxf(acc.y + b.y, 0.f);
    o.z = fmaxf(acc.z + b.z, 0.f);
    o.w = fmaxf(acc.w + b.w, 0.f);
    *(float4*)&g_h1[(size_t)c * 128 + lane * 4] = o;
}

// ---------------- GEMM2 (tf32): xt2[n,16] = h1[n,128] @ W2[128,16] ----------------
__global__ __launch_bounds__(256, 2) void k_gemm2(const float* __restrict__ W2, int n) {
    __shared__ float Hs[32][132];
    __shared__ float Ws2[32][20];
    int tid = threadIdx.x, lane = tid & 31, wid = tid >> 5;
    int m0 = blockIdx.x * 128;
    int wm = wid * 16;

    float acc[2][4];
#pragma unroll
    for (int nt = 0; nt < 2; nt++)
#pragma unroll
        for (int q = 0; q < 4; q++) acc[nt][q] = 0.f;

    int lm = tid & 127;
    int lkq = (tid >> 7) * 16;
    int wkk = tid >> 3, wc = (tid & 7) * 2;

    for (int k0 = 0; k0 < 128; k0 += 32) {
        float4 h[4];
        if (m0 + lm < n) {
            const float* hp = &g_h1[(size_t)(m0 + lm) * 128 + k0 + lkq];
#pragma unroll
            for (int j = 0; j < 4; j++) h[j] = *(const float4*)(hp + j * 4);
        } else {
#pragma unroll
            for (int j = 0; j < 4; j++) h[j] = make_float4(0.f, 0.f, 0.f, 0.f);
        }
#pragma unroll
        for (int j = 0; j < 4; j++) {
            Hs[lkq + j * 4 + 0][lm] = f2tf(h[j].x);
            Hs[lkq + j * 4 + 1][lm] = f2tf(h[j].y);
            Hs[lkq + j * 4 + 2][lm] = f2tf(h[j].z);
            Hs[lkq + j * 4 + 3][lm] = f2tf(h[j].w);
        }
        Ws2[wkk][wc]     = f2tf(W2[(size_t)(k0 + wkk) * 16 + wc]);
        Ws2[wkk][wc + 1] = f2tf(W2[(size_t)(k0 + wkk) * 16 + wc + 1]);
        __syncthreads();

#pragma unroll
        for (int kk = 0; kk < 32; kk += 8) {
            int ar = lane >> 2, ak = kk + (lane & 3);
            uint32_t a[4];
            a[0] = __float_as_uint(Hs[ak][wm + ar]);
            a[1] = __float_as_uint(Hs[ak][wm + ar + 8]);
            a[2] = __float_as_uint(Hs[ak + 4][wm + ar]);
            a[3] = __float_as_uint(Hs[ak + 4][wm + ar + 8]);
            uint32_t b0[2], b1[2];
            b0[0] = __float_as_uint(Ws2[ak][ar]);
            b0[1] = __float_as_uint(Ws2[ak + 4][ar]);
            b1[0] = __float_as_uint(Ws2[ak][8 + ar]);
            b1[1] = __float_as_uint(Ws2[ak + 4][8 + ar]);
            mma_tf32(acc[0], a, b0);
            mma_tf32(acc[1], a, b1);
        }
        __syncthreads();
    }

    int ar = lane >> 2, ac = (lane & 3) * 2;
#pragma unroll
    for (int nt = 0; nt < 2; nt++) {
        int r = m0 + wm + ar;
        int c = nt * 8 + ac;
        if (r < n)
            *(float2*)&g_xt2[(size_t)r * 16 + c] = make_float2(acc[nt][0], acc[nt][1]);
        if (r + 8 < n)
            *(float2*)&g_xt2[(size_t)(r + 8) * 16 + c] = make_float2(acc[nt][2], acc[nt][3]);
    }
}

__global__ void k_alar2(const float* __restrict__ att, int n) {
    int t = blockIdx.x * blockDim.x + threadIdx.x;
    if (t >= n) return;
    const float* xr = &g_xt2[(size_t)t * 16];
    float al = 0.f, ar = 0.f;
#pragma unroll
    for (int k = 0; k < 16; k += 4) {
        float4 v  = *(const float4*)&xr[k];
        float4 wl = *(const float4*)&att[k];
        float4 wr = *(const float4*)&att[16 + k];
        al += v.x * wl.x + v.y * wl.y + v.z * wl.z + v.w * wl.w;
        ar += v.x * wr.x + v.y * wr.y + v.z * wr.z + v.w * wr.w;
    }
    g_al2[t] = al;
    g_ar2[t] = ar;
}

// ---------------- fused softmax + aggregation layer2 (warp per node) ----------------
__global__ void k_agg2(const float* __restrict__ b2, int n, float* __restrict__ out) {
    int w = (blockIdx.x * blockDim.x + threadIdx.x) >> 5;
    if (w >= n) return;
    int lane = threadIdx.x & 31;
    int c = w;
    float dc = g_dinv[c];
    float alc = g_al2[c];
    int beg = g_off[c], end = g_off[c + 1];

    // pass 1: denominator
    float ps = 0.f;
    for (int j = beg + lane; j < end; j += 32) {
        int r = __ldg(&g_adj[j]);
        ps += __expf(lrelu(alc + g_ar2[r]));
    }
#pragma unroll
    for (int d = 16; d > 0; d >>= 1)
        ps += __shfl_xor_sync(0xffffffffu, ps, d);
    float se = __expf(lrelu(alc + g_ar2[c]));
    float rs = __fdividef(1.0f, ps + se + 1e-16f);

    // pass 2: lanes 0-15 cover channels
    int ch = lane & 15;
    float acc = dc * dc * se * rs * g_xt2[(size_t)c * 16 + ch];
#pragma unroll 2
    for (int j = beg; j < end; j++) {
        int r = __ldg(&g_adj[j]);
        float ex = __expf(lrelu(alc + g_ar2[r]));
        float coef = g_dinv[r] * dc * ex * rs;
        acc += coef * g_xt2[(size_t)r * 16 + ch];
    }
    if (lane < 16) out[(size_t)c * 16 + ch] = acc + b2[ch];
}

// ---------------- launch ----------------
extern "C" void kernel_launch(void* const* d_in, const int* in_sizes, int n_in,
                              void* d_out, int out_size) {
    const float* x    = (const float*)d_in[0];
    const int*   ei   = (const int*)d_in[1];
    const float* W1   = (const float*)d_in[2];
    const float* att1 = (const float*)d_in[3];
    const float* b1   = (const float*)d_in[4];
    const float* W2   = (const float*)d_in[5];
    const float* att2 = (const float*)d_in[6];
    const float* b2   = (const float*)d_in[7];
    float* out = (float*)d_out;

    int n = in_sizes[0] / 256;
    int e = in_sizes[1] / 2;
    int nb = (n + 1023) / 1024;

    const int T = 256;
    k_init<<<(n + T - 1) / T, T>>>(n);
    k_deg_count<<<(e + T - 1) / T, T>>>(ei, e);
    k_dinv<<<(n + T - 1) / T, T>>>(n);
    k_scan_blocks<<<nb, 1024>>>(n);
    k_scan_tops<<<1, 128>>>(nb);
    k_scan_add<<<nb, 1024>>>(n, e);
    k_scatter<<<(e + T - 1) / T, T>>>(ei, e);

    k_gemm1<<<(n + 127) / 128, 256>>>(x, W1, n);
    k_alar1<<<(n * 4 + T - 1) / T, T>>>(att1, n);
    k_agg1<<<(n * 32 + 255) / 256, 256>>>(b1, n);

    k_gemm2<<<(n + 127) / 128, 256>>>(W2, n);
    k_alar2<<<(n + T - 1) / T, T>>>(att2, n);
    k_agg2<<<(n * 32 + 255) / 256, 256>>>(b2, n, out);
}

// round 6
// speedup vs baseline: 3.1229x; 1.1353x over previous
#include <cuda_runtime.h>
#include <math.h>
#include <stdint.h>

#define NN 100000
#define EE 1600000
#define NB_SCAN ((NN + 1023) / 1024)

// ---------------- scratch (static device globals) ----------------
__device__ float    g_deg[NN];
__device__ float    g_dinv[NN];
__device__ float    g_xt1[(size_t)NN * 128];
__device__ float    g_al1[NN * 4];
__device__ float    g_ar1[NN * 4];
__device__ float    g_h1[(size_t)NN * 128];
__device__ float    g_xt2[NN * 16];
__device__ float    g_al2[NN];
__device__ float    g_ar2[NN];
// CSR by destination (col)
__device__ int      g_cnt[NN];
__device__ int      g_off[NN + 1];
__device__ int      g_wpos[NN];
__device__ int      g_bsum[NB_SCAN + 1];
__device__ int      g_adj[EE];     // source row only

__device__ __forceinline__ float lrelu(float a) { return a >= 0.f ? a : 0.2f * a; }

__device__ __forceinline__ float f2tf(float f) {
    uint32_t u;
    asm("cvt.rna.tf32.f32 %0, %1;" : "=r"(u) : "f"(f));
    return __uint_as_float(u);
}

__device__ __forceinline__ void mma_tf32(float* c, const uint32_t* a, const uint32_t* b) {
    asm volatile(
        "mma.sync.aligned.m16n8k8.row.col.f32.tf32.tf32.f32 "
        "{%0,%1,%2,%3}, {%4,%5,%6,%7}, {%8,%9}, {%0,%1,%2,%3};"
        : "+f"(c[0]), "+f"(c[1]), "+f"(c[2]), "+f"(c[3])
        : "r"(a[0]), "r"(a[1]), "r"(a[2]), "r"(a[3]), "r"(b[0]), "r"(b[1]));
}

// ---------------- init ----------------
__global__ void k_init(int n) {
    int i = blockIdx.x * blockDim.x + threadIdx.x;
    if (i < n) { g_deg[i] = 1.0f; g_cnt[i] = 0; }
}

__global__ void k_deg_count(const int* __restrict__ ei, int e) {
    int i = blockIdx.x * blockDim.x + threadIdx.x;
    if (i < e) {
        atomicAdd(&g_deg[ei[i]], 1.0f);
        atomicAdd(&g_cnt[ei[e + i]], 1);
    }
}

__global__ void k_dinv(int n) {
    int i = blockIdx.x * blockDim.x + threadIdx.x;
    if (i < n) g_dinv[i] = rsqrtf(g_deg[i]);
}

// ---------------- multi-block exclusive scan over g_cnt ----------------
__global__ void k_scan_blocks(int n) {
    __shared__ int warpsums[32];
    int i = blockIdx.x * 1024 + threadIdx.x;
    int lane = threadIdx.x & 31, wid = threadIdx.x >> 5;
    int v = (i < n) ? g_cnt[i] : 0;
    int s = v;
#pragma unroll
    for (int d = 1; d < 32; d <<= 1) {
        int t = __shfl_up_sync(0xffffffffu, s, d);
        if (lane >= d) s += t;
    }
    if (lane == 31) warpsums[wid] = s;
    __syncthreads();
    if (wid == 0) {
        int ws = warpsums[lane];
#pragma unroll
        for (int d = 1; d < 32; d <<= 1) {
            int t = __shfl_up_sync(0xffffffffu, ws, d);
            if (lane >= d) ws += t;
        }
        warpsums[lane] = ws;
    }
    __syncthreads();
    int base = (wid > 0) ? warpsums[wid - 1] : 0;
    int exc = s - v + base;
    if (i < n) g_off[i] = exc;
    if (threadIdx.x == 1023) g_bsum[blockIdx.x] = exc + v;
}

__global__ void k_scan_tops(int nb) {
    __shared__ int warpsums[4];
    int lane = threadIdx.x & 31, wid = threadIdx.x >> 5;
    int v = (threadIdx.x < nb) ? g_bsum[threadIdx.x] : 0;
    int s = v;
#pragma unroll
    for (int d = 1; d < 32; d <<= 1) {
        int t = __shfl_up_sync(0xffffffffu, s, d);
        if (lane >= d) s += t;
    }
    if (lane == 31) warpsums[wid] = s;
    __syncthreads();
    int base = 0;
#pragma unroll
    for (int w = 0; w < 4; w++) if (w < wid) base += warpsums[w];
    if (threadIdx.x < nb) g_bsum[threadIdx.x] = s - v + base;
}

__global__ void k_scan_add(int n, int e) {
    int i = blockIdx.x * 1024 + threadIdx.x;
    if (i < n) {
        int o = g_off[i] + g_bsum[blockIdx.x];
        g_off[i] = o;
        g_wpos[i] = o;
    }
    if (i == 0) g_off[n] = e;
}

__global__ void k_scatter(const int* __restrict__ ei, int e) {
    int i = blockIdx.x * blockDim.x + threadIdx.x;
    if (i >= e) return;
    int r = ei[i], c = ei[e + i];
    int p = atomicAdd(&g_wpos[c], 1);
    g_adj[p] = r;
}

// ---------------- GEMM1 (tf32) + fused alar1 epilogue ----------------
// xt1[n,128] = X[n,256] @ W1[256,128]; al1/ar1[n,h] = xt1[n,h*32:+32] . att1[h]
__global__ __launch_bounds__(256, 2) void k_gemm1(const float* __restrict__ X,
                                                  const float* __restrict__ W,
                                                  const float* __restrict__ att, int n) {
    __shared__ float Xs[16][132];
    __shared__ float Ws[16][132];
    int tid = threadIdx.x, lane = tid & 31, wid = tid >> 5;
    int m0 = blockIdx.x * 128;
    int wm = (wid & 1) * 64, wn = (wid >> 1) * 32;

    float acc[4][4][4];
#pragma unroll
    for (int mt = 0; mt < 4; mt++)
#pragma unroll
        for (int nt = 0; nt < 4; nt++)
#pragma unroll
            for (int q = 0; q < 4; q++) acc[mt][nt][q] = 0.f;

    int lm = tid & 127;
    int lkq = (tid >> 7) * 8;
    int wk = tid >> 4;
    int wq = (tid & 15) * 8;

    bool mok = (m0 + lm < n);
    const float* xbase = &X[(size_t)(m0 + lm) * 256 + lkq];
    const float* wbase = &W[(size_t)wk * 128 + wq];

    float4 v0 = make_float4(0.f, 0.f, 0.f, 0.f), v1 = v0;
    if (mok) { v0 = *(const float4*)xbase; v1 = *(const float4*)(xbase + 4); }
    float4 w0 = *(const float4*)wbase;
    float4 w1 = *(const float4*)(wbase + 4);

    for (int k0 = 0; k0 < 256; k0 += 16) {
        Xs[lkq + 0][lm] = f2tf(v0.x); Xs[lkq + 1][lm] = f2tf(v0.y);
        Xs[lkq + 2][lm] = f2tf(v0.z); Xs[lkq + 3][lm] = f2tf(v0.w);
        Xs[lkq + 4][lm] = f2tf(v1.x); Xs[lkq + 5][lm] = f2tf(v1.y);
        Xs[lkq + 6][lm] = f2tf(v1.z); Xs[lkq + 7][lm] = f2tf(v1.w);
        Ws[wk][wq + 0] = f2tf(w0.x); Ws[wk][wq + 1] = f2tf(w0.y);
        Ws[wk][wq + 2] = f2tf(w0.z); Ws[wk][wq + 3] = f2tf(w0.w);
        Ws[wk][wq + 4] = f2tf(w1.x); Ws[wk][wq + 5] = f2tf(w1.y);
        Ws[wk][wq + 6] = f2tf(w1.z); Ws[wk][wq + 7] = f2tf(w1.w);
        __syncthreads();

        if (k0 + 16 < 256) {
            const float* xp = xbase + k0 + 16;
            const float* wp = wbase + (size_t)(k0 + 16) * 128;
            if (mok) { v0 = *(const float4*)xp; v1 = *(const float4*)(xp + 4); }
            w0 = *(const float4*)wp;
            w1 = *(const float4*)(wp + 4);
        }

#pragma unroll
        for (int kk = 0; kk < 16; kk += 8) {
            int ar = lane >> 2, ak = kk + (lane & 3);
            uint32_t a[4][4], b[4][2];
#pragma unroll
            for (int mt = 0; mt < 4; mt++) {
                int r = wm + mt * 16 + ar;
                a[mt][0] = __float_as_uint(Xs[ak][r]);
                a[mt][1] = __float_as_uint(Xs[ak][r + 8]);
                a[mt][2] = __float_as_uint(Xs[ak + 4][r]);
                a[mt][3] = __float_as_uint(Xs[ak + 4][r + 8]);
            }
#pragma unroll
            for (int nt = 0; nt < 4; nt++) {
                int c = wn + nt * 8 + ar;
                b[nt][0] = __float_as_uint(Ws[ak][c]);
                b[nt][1] = __float_as_uint(Ws[ak + 4][c]);
            }
#pragma unroll
            for (int mt = 0; mt < 4; mt++)
#pragma unroll
                for (int nt = 0; nt < 4; nt++)
                    mma_tf32(acc[mt][nt], a[mt], b[nt]);
        }
        __syncthreads();
    }

    int ar = lane >> 2, ac = (lane & 3) * 2;
#pragma unroll
    for (int mt = 0; mt < 4; mt++) {
        int r = m0 + wm + mt * 16 + ar;
#pragma unroll
        for (int nt = 0; nt < 4; nt++) {
            int c = wn + nt * 8 + ac;
            if (r < n)
                *(float2*)&g_xt1[(size_t)r * 128 + c] = make_float2(acc[mt][nt][0], acc[mt][nt][1]);
            if (r + 8 < n)
                *(float2*)&g_xt1[(size_t)(r + 8) * 128 + c] = make_float2(acc[mt][nt][2], acc[mt][nt][3]);
        }
    }

    // ---- fused alar1 epilogue: this warp's 32 cols == head hh ----
    int hh = wid >> 1;
    float wlv[8], wrv[8];
#pragma unroll
    for (int nt = 0; nt < 4; nt++) {
        int cc = nt * 8 + ac;
        wlv[nt * 2 + 0] = att[hh * 64 + cc];
        wlv[nt * 2 + 1] = att[hh * 64 + cc + 1];
        wrv[nt * 2 + 0] = att[hh * 64 + 32 + cc];
        wrv[nt * 2 + 1] = att[hh * 64 + 32 + cc + 1];
    }
#pragma unroll
    for (int mt = 0; mt < 4; mt++) {
        float alp0 = 0.f, arp0 = 0.f, alp1 = 0.f, arp1 = 0.f;
#pragma unroll
        for (int nt = 0; nt < 4; nt++) {
            alp0 += acc[mt][nt][0] * wlv[nt * 2] + acc[mt][nt][1] * wlv[nt * 2 + 1];
            arp0 += acc[mt][nt][0] * wrv[nt * 2] + acc[mt][nt][1] * wrv[nt * 2 + 1];
            alp1 += acc[mt][nt][2] * wlv[nt * 2] + acc[mt][nt][3] * wlv[nt * 2 + 1];
            arp1 += acc[mt][nt][2] * wrv[nt * 2] + acc[mt][nt][3] * wrv[nt * 2 + 1];
        }
#pragma unroll
        for (int d = 1; d <= 2; d <<= 1) {
            alp0 += __shfl_xor_sync(0xffffffffu, alp0, d);
            arp0 += __shfl_xor_sync(0xffffffffu, arp0, d);
            alp1 += __shfl_xor_sync(0xffffffffu, alp1, d);
            arp1 += __shfl_xor_sync(0xffffffffu, arp1, d);
        }
        if ((lane & 3) == 0) {
            int r = m0 + wm + mt * 16 + ar;
            if (r < n)     { g_al1[r * 4 + hh] = alp0;       g_ar1[r * 4 + hh] = arp0; }
            if (r + 8 < n) { g_al1[(r + 8) * 4 + hh] = alp1; g_ar1[(r + 8) * 4 + hh] = arp1; }
        }
    }
}

// ---------------- single-sweep fused softmax + aggregation layer1 ----------------
__global__ void k_agg1(const float* __restrict__ b1, int n) {
    __shared__ float sw[8][32][4];
    __shared__ int   sr[8][32];
    int w = (blockIdx.x * blockDim.x + threadIdx.x) >> 5;
    if (w >= n) return;
    int lane = threadIdx.x & 31;
    int wz = (threadIdx.x >> 5) & 7;
    int c = w;
    float dc = g_dinv[c];
    float4 alc = *(const float4*)&g_al1[c * 4];
    float4 arc = *(const float4*)&g_ar1[c * 4];
    int beg = g_off[c], end = g_off[c + 1];
    int h = lane >> 3;

    float4 ps = make_float4(0.f, 0.f, 0.f, 0.f);
    float4 acc = make_float4(0.f, 0.f, 0.f, 0.f);

    for (int t0 = beg; t0 < end; t0 += 32) {
        int j = t0 + lane;
        if (j < end) {
            int r = __ldg(&g_adj[j]);
            float4 ar4 = *(const float4*)&g_ar1[r * 4];
            float di = g_dinv[r];
            float e0 = __expf(lrelu(alc.x + ar4.x));
            float e1 = __expf(lrelu(alc.y + ar4.y));
            float e2 = __expf(lrelu(alc.z + ar4.z));
            float e3 = __expf(lrelu(alc.w + ar4.w));
            ps.x += e0; ps.y += e1; ps.z += e2; ps.w += e3;
            sw[wz][lane][0] = di * e0;
            sw[wz][lane][1] = di * e1;
            sw[wz][lane][2] = di * e2;
            sw[wz][lane][3] = di * e3;
            sr[wz][lane] = r;
        }
        __syncwarp();
        int cnt = min(32, end - t0);
#pragma unroll 4
        for (int u = 0; u < cnt; u++) {
            int r = sr[wz][u];
            float wh = sw[wz][u][h];
            float4 xj = *(const float4*)&g_xt1[(size_t)r * 128 + lane * 4];
            acc.x += wh * xj.x; acc.y += wh * xj.y;
            acc.z += wh * xj.z; acc.w += wh * xj.w;
        }
        __syncwarp();
    }

#pragma unroll
    for (int d = 16; d > 0; d >>= 1) {
        ps.x += __shfl_xor_sync(0xffffffffu, ps.x, d);
        ps.y += __shfl_xor_sync(0xffffffffu, ps.y, d);
        ps.z += __shfl_xor_sync(0xffffffffu, ps.z, d);
        ps.w += __shfl_xor_sync(0xffffffffu, ps.w, d);
    }
    float se0 = __expf(lrelu(alc.x + arc.x));
    float se1 = __expf(lrelu(alc.y + arc.y));
    float se2 = __expf(lrelu(alc.z + arc.z));
    float se3 = __expf(lrelu(alc.w + arc.w));
    float rs0 = __fdividef(1.0f, ps.x + se0 + 1e-16f);
    float rs1 = __fdividef(1.0f, ps.y + se1 + 1e-16f);
    float rs2 = __fdividef(1.0f, ps.z + se2 + 1e-16f);
    float rs3 = __fdividef(1.0f, ps.w + se3 + 1e-16f);
    float seh = h < 2 ? (h == 0 ? se0 : se1) : (h == 2 ? se2 : se3);
    float rsh = h < 2 ? (h == 0 ? rs0 : rs1) : (h == 2 ? rs2 : rs3);

    // self term (unnormalized weight = dc * seh), then scale by dc*rsh
    float4 xc = *(const float4*)&g_xt1[(size_t)c * 128 + lane * 4];
    float wself = dc * seh;
    acc.x += wself * xc.x; acc.y += wself * xc.y;
    acc.z += wself * xc.z; acc.w += wself * xc.w;
    float sc = dc * rsh;

    float4 b = *(const float4*)&b1[lane * 4];
    float4 o;
    o.x = fmaxf(acc.x * sc + b.x, 0.f);
    o.y = fmaxf(acc.y * sc + b.y, 0.f);
    o.z = fmaxf(acc.z * sc + b.z, 0.f);
    o.w = fmaxf(acc.w * sc + b.w, 0.f);
    *(float4*)&g_h1[(size_t)c * 128 + lane * 4] = o;
}

// ---------------- GEMM2 (tf32): xt2[n,16] = h1[n,128] @ W2[128,16] ----------------
__global__ __launch_bounds__(256, 2) void k_gemm2(const float* __restrict__ W2, int n) {
    __shared__ float Hs[32][132];
    __shared__ float Ws2[32][20];
    int tid = threadIdx.x, lane = tid & 31, wid = tid >> 5;
    int m0 = blockIdx.x * 128;
    int wm = wid * 16;

    float acc[2][4];
#pragma unroll
    for (int nt = 0; nt < 2; nt++)
#pragma unroll
        for (int q = 0; q < 4; q++) acc[nt][q] = 0.f;

    int lm = tid & 127;
    int lkq = (tid >> 7) * 16;
    int wkk = tid >> 3, wc = (tid & 7) * 2;

    for (int k0 = 0; k0 < 128; k0 += 32) {
        float4 h[4];
        if (m0 + lm < n) {
            const float* hp = &g_h1[(size_t)(m0 + lm) * 128 + k0 + lkq];
#pragma unroll
            for (int j = 0; j < 4; j++) h[j] = *(const float4*)(hp + j * 4);
        } else {
#pragma unroll
            for (int j = 0; j < 4; j++) h[j] = make_float4(0.f, 0.f, 0.f, 0.f);
        }
#pragma unroll
        for (int j = 0; j < 4; j++) {
            Hs[lkq + j * 4 + 0][lm] = f2tf(h[j].x);
            Hs[lkq + j * 4 + 1][lm] = f2tf(h[j].y);
            Hs[lkq + j * 4 + 2][lm] = f2tf(h[j].z);
            Hs[lkq + j * 4 + 3][lm] = f2tf(h[j].w);
        }
        Ws2[wkk][wc]     = f2tf(W2[(size_t)(k0 + wkk) * 16 + wc]);
        Ws2[wkk][wc + 1] = f2tf(W2[(size_t)(k0 + wkk) * 16 + wc + 1]);
        __syncthreads();

#pragma unroll
        for (int kk = 0; kk < 32; kk += 8) {
            int ar = lane >> 2, ak = kk + (lane & 3);
            uint32_t a[4];
            a[0] = __float_as_uint(Hs[ak][wm + ar]);
            a[1] = __float_as_uint(Hs[ak][wm + ar + 8]);
            a[2] = __float_as_uint(Hs[ak + 4][wm + ar]);
            a[3] = __float_as_uint(Hs[ak + 4][wm + ar + 8]);
            uint32_t b0[2], b1[2];
            b0[0] = __float_as_uint(Ws2[ak][ar]);
            b0[1] = __float_as_uint(Ws2[ak + 4][ar]);
            b1[0] = __float_as_uint(Ws2[ak][8 + ar]);
            b1[1] = __float_as_uint(Ws2[ak + 4][8 + ar]);
            mma_tf32(acc[0], a, b0);
            mma_tf32(acc[1], a, b1);
        }
        __syncthreads();
    }

    int ar = lane >> 2, ac = (lane & 3) * 2;
#pragma unroll
    for (int nt = 0; nt < 2; nt++) {
        int r = m0 + wm + ar;
        int c = nt * 8 + ac;
        if (r < n)
            *(float2*)&g_xt2[(size_t)r * 16 + c] = make_float2(acc[nt][0], acc[nt][1]);
        if (r + 8 < n)
            *(float2*)&g_xt2[(size_t)(r + 8) * 16 + c] = make_float2(acc[nt][2], acc[nt][3]);
    }
}

__global__ void k_alar2(const float* __restrict__ att, int n) {
    int t = blockIdx.x * blockDim.x + threadIdx.x;
    if (t >= n) return;
    const float* xr = &g_xt2[(size_t)t * 16];
    float al = 0.f, ar = 0.f;
#pragma unroll
    for (int k = 0; k < 16; k += 4) {
        float4 v  = *(const float4*)&xr[k];
        float4 wl = *(const float4*)&att[k];
        float4 wr = *(const float4*)&att[16 + k];
        al += v.x * wl.x + v.y * wl.y + v.z * wl.z + v.w * wl.w;
        ar += v.x * wr.x + v.y * wr.y + v.z * wr.z + v.w * wr.w;
    }
    g_al2[t] = al;
    g_ar2[t] = ar;
}

// ---------------- single-sweep fused softmax + aggregation layer2 ----------------
__global__ void k_agg2(const float* __restrict__ b2, int n, float* __restrict__ out) {
    __shared__ float sw2[8][32];
    __shared__ int   sr2[8][32];
    int w = (blockIdx.x * blockDim.x + threadIdx.x) >> 5;
    if (w >= n) return;
    int lane = threadIdx.x & 31;
    int wz = (threadIdx.x >> 5) & 7;
    int c = w;
    float dc = g_dinv[c];
    float alc = g_al2[c];
    int beg = g_off[c], end = g_off[c + 1];
    int ch = lane & 15;

    float ps = 0.f, acc = 0.f;
    for (int t0 = beg; t0 < end; t0 += 32) {
        int j = t0 + lane;
        if (j < end) {
            int r = __ldg(&g_adj[j]);
            float e = __expf(lrelu(alc + g_ar2[r]));
            ps += e;
            sw2[wz][lane] = g_dinv[r] * e;
            sr2[wz][lane] = r;
        }
        __syncwarp();
        int cnt = min(32, end - t0);
#pragma unroll 4
        for (int u = 0; u < cnt; u += 2) {
            int uu = u + (lane >> 4);
            if (uu < cnt) {
                int r = sr2[wz][uu];
                acc += sw2[wz][uu] * g_xt2[(size_t)r * 16 + ch];
            }
        }
        __syncwarp();
    }

#pragma unroll
    for (int d = 16; d > 0; d >>= 1)
        ps += __shfl_xor_sync(0xffffffffu, ps, d);
    float se = __expf(lrelu(alc + g_ar2[c]));
    float rs = __fdividef(1.0f, ps + se + 1e-16f);

    // fold the two half-warp partial sums, then add self once
    acc += __shfl_xor_sync(0xffffffffu, acc, 16);
    acc += dc * se * g_xt2[(size_t)c * 16 + ch];
    if (lane < 16) out[(size_t)c * 16 + ch] = dc * rs * acc + b2[ch];
}

// ---------------- launch ----------------
extern "C" void kernel_launch(void* const* d_in, const int* in_sizes, int n_in,
                              void* d_out, int out_size) {
    const float* x    = (const float*)d_in[0];
    const int*   ei   = (const int*)d_in[1];
    const float* W1   = (const float*)d_in[2];
    const float* att1 = (const float*)d_in[3];
    const float* b1   = (const float*)d_in[4];
    const float* W2   = (const float*)d_in[5];
    const float* att2 = (const float*)d_in[6];
    const float* b2   = (const float*)d_in[7];
    float* out = (float*)d_out;

    int n = in_sizes[0] / 256;
    int e = in_sizes[1] / 2;
    int nb = (n + 1023) / 1024;

    const int T = 256;
    k_init<<<(n + T - 1) / T, T>>>(n);
    k_deg_count<<<(e + T - 1) / T, T>>>(ei, e);
    k_dinv<<<(n + T - 1) / T, T>>>(n);
    k_scan_blocks<<<nb, 1024>>>(n);
    k_scan_tops<<<1, 128>>>(nb);
    k_scan_add<<<nb, 1024>>>(n, e);
    k_scatter<<<(e + T - 1) / T, T>>>(ei, e);

    k_gemm1<<<(n + 127) / 128, 256>>>(x, W1, att1, n);
    k_agg1<<<(n * 32 + 255) / 256, 256>>>(b1, n);

    k_gemm2<<<(n + 127) / 128, 256>>>(W2, n);
    k_alar2<<<(n + T - 1) / T, T>>>(att2, n);
    k_agg2<<<(n * 32 + 255) / 256, 256>>>(b2, n, out);
}

// round 7
// speedup vs baseline: 3.3406x; 1.0697x over previous
#include <cuda_runtime.h>
#include <cuda_fp16.h>
#include <math.h>
#include <stdint.h>

#define NN 100000
#define EE 1600000
#define NB_SCAN ((NN + 1023) / 1024)

// ---------------- scratch (static device globals) ----------------
__device__ float    g_deg[NN];
__device__ float    g_dinv[NN];
__device__ __half   g_xt1[(size_t)NN * 128];
__device__ float    g_al1[NN * 4];
__device__ float    g_ar1[NN * 4];
__device__ __half   g_h1[(size_t)NN * 128];
__device__ __half   g_xt2[NN * 16];
__device__ float    g_al2[NN];
__device__ float    g_ar2[NN];
// CSR by destination (col)
__device__ int      g_cnt[NN];
__device__ int      g_off[NN + 1];
__device__ int      g_wpos[NN];
__device__ int      g_bsum[NB_SCAN + 1];
__device__ int      g_adj[EE];     // source row only

__device__ __forceinline__ float lrelu(float a) { return a >= 0.f ? a : 0.2f * a; }

__device__ __forceinline__ float f2tf(float f) {
    uint32_t u;
    asm("cvt.rna.tf32.f32 %0, %1;" : "=r"(u) : "f"(f));
    return __uint_as_float(u);
}

__device__ __forceinline__ void mma_tf32(float* c, const uint32_t* a, const uint32_t* b) {
    asm volatile(
        "mma.sync.aligned.m16n8k8.row.col.f32.tf32.tf32.f32 "
        "{%0,%1,%2,%3}, {%4,%5,%6,%7}, {%8,%9}, {%0,%1,%2,%3};"
        : "+f"(c[0]), "+f"(c[1]), "+f"(c[2]), "+f"(c[3])
        : "r"(a[0]), "r"(a[1]), "r"(a[2]), "r"(a[3]), "r"(b[0]), "r"(b[1]));
}

// ---------------- init ----------------
__global__ void k_init(int n) {
    int i = blockIdx.x * blockDim.x + threadIdx.x;
    if (i < n) { g_deg[i] = 1.0f; g_cnt[i] = 0; }
}

__global__ void k_deg_count(const int* __restrict__ ei, int e) {
    int i = blockIdx.x * blockDim.x + threadIdx.x;
    if (i < e) {
        atomicAdd(&g_deg[ei[i]], 1.0f);
        atomicAdd(&g_cnt[ei[e + i]], 1);
    }
}

__global__ void k_dinv(int n) {
    int i = blockIdx.x * blockDim.x + threadIdx.x;
    if (i < n) g_dinv[i] = rsqrtf(g_deg[i]);
}

// ---------------- multi-block exclusive scan over g_cnt ----------------
__global__ void k_scan_blocks(int n) {
    __shared__ int warpsums[32];
    int i = blockIdx.x * 1024 + threadIdx.x;
    int lane = threadIdx.x & 31, wid = threadIdx.x >> 5;
    int v = (i < n) ? g_cnt[i] : 0;
    int s = v;
#pragma unroll
    for (int d = 1; d < 32; d <<= 1) {
        int t = __shfl_up_sync(0xffffffffu, s, d);
        if (lane >= d) s += t;
    }
    if (lane == 31) warpsums[wid] = s;
    __syncthreads();
    if (wid == 0) {
        int ws = warpsums[lane];
#pragma unroll
        for (int d = 1; d < 32; d <<= 1) {
            int t = __shfl_up_sync(0xffffffffu, ws, d);
            if (lane >= d) ws += t;
        }
        warpsums[lane] = ws;
    }
    __syncthreads();
    int base = (wid > 0) ? warpsums[wid - 1] : 0;
    int exc = s - v + base;
    if (i < n) g_off[i] = exc;
    if (threadIdx.x == 1023) g_bsum[blockIdx.x] = exc + v;
}

__global__ void k_scan_tops(int nb) {
    __shared__ int warpsums[4];
    int lane = threadIdx.x & 31, wid = threadIdx.x >> 5;
    int v = (threadIdx.x < nb) ? g_bsum[threadIdx.x] : 0;
    int s = v;
#pragma unroll
    for (int d = 1; d < 32; d <<= 1) {
        int t = __shfl_up_sync(0xffffffffu, s, d);
        if (lane >= d) s += t;
    }
    if (lane == 31) warpsums[wid] = s;
    __syncthreads();
    int base = 0;
#pragma unroll
    for (int w = 0; w < 4; w++) if (w < wid) base += warpsums[w];
    if (threadIdx.x < nb) g_bsum[threadIdx.x] = s - v + base;
}

__global__ void k_scan_add(int n, int e) {
    int i = blockIdx.x * 1024 + threadIdx.x;
    if (i < n) {
        int o = g_off[i] + g_bsum[blockIdx.x];
        g_off[i] = o;
        g_wpos[i] = o;
    }
    if (i == 0) g_off[n] = e;
}

__global__ void k_scatter(const int* __restrict__ ei, int e) {
    int i = blockIdx.x * blockDim.x + threadIdx.x;
    if (i >= e) return;
    int r = ei[i], c = ei[e + i];
    int p = atomicAdd(&g_wpos[c], 1);
    g_adj[p] = r;
}

// ---------------- GEMM1 (tf32) + fused alar1 epilogue, fp16 xt1 out ----------------
__global__ __launch_bounds__(256, 2) void k_gemm1(const float* __restrict__ X,
                                                  const float* __restrict__ W,
                                                  const float* __restrict__ att, int n) {
    __shared__ float Xs[16][132];
    __shared__ float Ws[16][132];
    int tid = threadIdx.x, lane = tid & 31, wid = tid >> 5;
    int m0 = blockIdx.x * 128;
    int wm = (wid & 1) * 64, wn = (wid >> 1) * 32;

    float acc[4][4][4];
#pragma unroll
    for (int mt = 0; mt < 4; mt++)
#pragma unroll
        for (int nt = 0; nt < 4; nt++)
#pragma unroll
            for (int q = 0; q < 4; q++) acc[mt][nt][q] = 0.f;

    int lm = tid & 127;
    int lkq = (tid >> 7) * 8;
    int wk = tid >> 4;
    int wq = (tid & 15) * 8;

    bool mok = (m0 + lm < n);
    const float* xbase = &X[(size_t)(m0 + lm) * 256 + lkq];
    const float* wbase = &W[(size_t)wk * 128 + wq];

    float4 v0 = make_float4(0.f, 0.f, 0.f, 0.f), v1 = v0;
    if (mok) { v0 = *(const float4*)xbase; v1 = *(const float4*)(xbase + 4); }
    float4 w0 = *(const float4*)wbase;
    float4 w1 = *(const float4*)(wbase + 4);

    for (int k0 = 0; k0 < 256; k0 += 16) {
        Xs[lkq + 0][lm] = f2tf(v0.x); Xs[lkq + 1][lm] = f2tf(v0.y);
        Xs[lkq + 2][lm] = f2tf(v0.z); Xs[lkq + 3][lm] = f2tf(v0.w);
        Xs[lkq + 4][lm] = f2tf(v1.x); Xs[lkq + 5][lm] = f2tf(v1.y);
        Xs[lkq + 6][lm] = f2tf(v1.z); Xs[lkq + 7][lm] = f2tf(v1.w);
        Ws[wk][wq + 0] = f2tf(w0.x); Ws[wk][wq + 1] = f2tf(w0.y);
        Ws[wk][wq + 2] = f2tf(w0.z); Ws[wk][wq + 3] = f2tf(w0.w);
        Ws[wk][wq + 4] = f2tf(w1.x); Ws[wk][wq + 5] = f2tf(w1.y);
        Ws[wk][wq + 6] = f2tf(w1.z); Ws[wk][wq + 7] = f2tf(w1.w);
        __syncthreads();

        if (k0 + 16 < 256) {
            const float* xp = xbase + k0 + 16;
            const float* wp = wbase + (size_t)(k0 + 16) * 128;
            if (mok) { v0 = *(const float4*)xp; v1 = *(const float4*)(xp + 4); }
            w0 = *(const float4*)wp;
            w1 = *(const float4*)(wp + 4);
        }

#pragma unroll
        for (int kk = 0; kk < 16; kk += 8) {
            int ar = lane >> 2, ak = kk + (lane & 3);
            uint32_t a[4][4], b[4][2];
#pragma unroll
            for (int mt = 0; mt < 4; mt++) {
                int r = wm + mt * 16 + ar;
                a[mt][0] = __float_as_uint(Xs[ak][r]);
                a[mt][1] = __float_as_uint(Xs[ak][r + 8]);
                a[mt][2] = __float_as_uint(Xs[ak + 4][r]);
                a[mt][3] = __float_as_uint(Xs[ak + 4][r + 8]);
            }
#pragma unroll
            for (int nt = 0; nt < 4; nt++) {
                int c = wn + nt * 8 + ar;
                b[nt][0] = __float_as_uint(Ws[ak][c]);
                b[nt][1] = __float_as_uint(Ws[ak + 4][c]);
            }
#pragma unroll
            for (int mt = 0; mt < 4; mt++)
#pragma unroll
                for (int nt = 0; nt < 4; nt++)
                    mma_tf32(acc[mt][nt], a[mt], b[nt]);
        }
        __syncthreads();
    }

    int ar = lane >> 2, ac = (lane & 3) * 2;
#pragma unroll
    for (int mt = 0; mt < 4; mt++) {
        int r = m0 + wm + mt * 16 + ar;
#pragma unroll
        for (int nt = 0; nt < 4; nt++) {
            int c = wn + nt * 8 + ac;
            if (r < n)
                *(__half2*)&g_xt1[(size_t)r * 128 + c] =
                    __floats2half2_rn(acc[mt][nt][0], acc[mt][nt][1]);
            if (r + 8 < n)
                *(__half2*)&g_xt1[(size_t)(r + 8) * 128 + c] =
                    __floats2half2_rn(acc[mt][nt][2], acc[mt][nt][3]);
        }
    }

    // ---- fused alar1 epilogue ----
    int hh = wid >> 1;
    float wlv[8], wrv[8];
#pragma unroll
    for (int nt = 0; nt < 4; nt++) {
        int cc = nt * 8 + ac;
        wlv[nt * 2 + 0] = att[hh * 64 + cc];
        wlv[nt * 2 + 1] = att[hh * 64 + cc + 1];
        wrv[nt * 2 + 0] = att[hh * 64 + 32 + cc];
        wrv[nt * 2 + 1] = att[hh * 64 + 32 + cc + 1];
    }
#pragma unroll
    for (int mt = 0; mt < 4; mt++) {
        float alp0 = 0.f, arp0 = 0.f, alp1 = 0.f, arp1 = 0.f;
#pragma unroll
        for (int nt = 0; nt < 4; nt++) {
            alp0 += acc[mt][nt][0] * wlv[nt * 2] + acc[mt][nt][1] * wlv[nt * 2 + 1];
            arp0 += acc[mt][nt][0] * wrv[nt * 2] + acc[mt][nt][1] * wrv[nt * 2 + 1];
            alp1 += acc[mt][nt][2] * wlv[nt * 2] + acc[mt][nt][3] * wlv[nt * 2 + 1];
            arp1 += acc[mt][nt][2] * wrv[nt * 2] + acc[mt][nt][3] * wrv[nt * 2 + 1];
        }
#pragma unroll
        for (int d = 1; d <= 2; d <<= 1) {
            alp0 += __shfl_xor_sync(0xffffffffu, alp0, d);
            arp0 += __shfl_xor_sync(0xffffffffu, arp0, d);
            alp1 += __shfl_xor_sync(0xffffffffu, alp1, d);
            arp1 += __shfl_xor_sync(0xffffffffu, arp1, d);
        }
        if ((lane & 3) == 0) {
            int r = m0 + wm + mt * 16 + ar;
            if (r < n)     { g_al1[r * 4 + hh] = alp0;       g_ar1[r * 4 + hh] = arp0; }
            if (r + 8 < n) { g_al1[(r + 8) * 4 + hh] = alp1; g_ar1[(r + 8) * 4 + hh] = arp1; }
        }
    }
}

// ---------------- single-sweep fused softmax + aggregation layer1 (fp16 gathers) ----------------
__global__ void k_agg1(const float* __restrict__ b1, int n) {
    __shared__ float sw[8][32][4];
    __shared__ int   sr[8][32];
    int w = (blockIdx.x * blockDim.x + threadIdx.x) >> 5;
    if (w >= n) return;
    int lane = threadIdx.x & 31;
    int wz = (threadIdx.x >> 5) & 7;
    int c = w;
    float dc = g_dinv[c];
    float4 alc = *(const float4*)&g_al1[c * 4];
    float4 arc = *(const float4*)&g_ar1[c * 4];
    int beg = g_off[c], end = g_off[c + 1];
    int h = lane >> 3;

    float4 ps = make_float4(0.f, 0.f, 0.f, 0.f);
    float4 acc = make_float4(0.f, 0.f, 0.f, 0.f);

    for (int t0 = beg; t0 < end; t0 += 32) {
        int j = t0 + lane;
        if (j < end) {
            int r = __ldg(&g_adj[j]);
            float4 ar4 = *(const float4*)&g_ar1[r * 4];
            float di = g_dinv[r];
            float e0 = __expf(lrelu(alc.x + ar4.x));
            float e1 = __expf(lrelu(alc.y + ar4.y));
            float e2 = __expf(lrelu(alc.z + ar4.z));
            float e3 = __expf(lrelu(alc.w + ar4.w));
            ps.x += e0; ps.y += e1; ps.z += e2; ps.w += e3;
            sw[wz][lane][0] = di * e0;
            sw[wz][lane][1] = di * e1;
            sw[wz][lane][2] = di * e2;
            sw[wz][lane][3] = di * e3;
            sr[wz][lane] = r;
        }
        __syncwarp();
        int cnt = min(32, end - t0);
#pragma unroll 4
        for (int u = 0; u < cnt; u++) {
            int r = sr[wz][u];
            float wh = sw[wz][u][h];
            uint2 u2 = *(const uint2*)&g_xt1[(size_t)r * 128 + lane * 4];
            float2 f0 = __half22float2(*(__half2*)&u2.x);
            float2 f1 = __half22float2(*(__half2*)&u2.y);
            acc.x += wh * f0.x; acc.y += wh * f0.y;
            acc.z += wh * f1.x; acc.w += wh * f1.y;
        }
        __syncwarp();
    }

#pragma unroll
    for (int d = 16; d > 0; d >>= 1) {
        ps.x += __shfl_xor_sync(0xffffffffu, ps.x, d);
        ps.y += __shfl_xor_sync(0xffffffffu, ps.y, d);
        ps.z += __shfl_xor_sync(0xffffffffu, ps.z, d);
        ps.w += __shfl_xor_sync(0xffffffffu, ps.w, d);
    }
    float se0 = __expf(lrelu(alc.x + arc.x));
    float se1 = __expf(lrelu(alc.y + arc.y));
    float se2 = __expf(lrelu(alc.z + arc.z));
    float se3 = __expf(lrelu(alc.w + arc.w));
    float rs0 = __fdividef(1.0f, ps.x + se0 + 1e-16f);
    float rs1 = __fdividef(1.0f, ps.y + se1 + 1e-16f);
    float rs2 = __fdividef(1.0f, ps.z + se2 + 1e-16f);
    float rs3 = __fdividef(1.0f, ps.w + se3 + 1e-16f);
    float seh = h < 2 ? (h == 0 ? se0 : se1) : (h == 2 ? se2 : se3);
    float rsh = h < 2 ? (h == 0 ? rs0 : rs1) : (h == 2 ? rs2 : rs3);

    uint2 uc = *(const uint2*)&g_xt1[(size_t)c * 128 + lane * 4];
    float2 c0 = __half22float2(*(__half2*)&uc.x);
    float2 c1 = __half22float2(*(__half2*)&uc.y);
    float wself = dc * seh;
    acc.x += wself * c0.x; acc.y += wself * c0.y;
    acc.z += wself * c1.x; acc.w += wself * c1.y;
    float sc = dc * rsh;

    float4 b = *(const float4*)&b1[lane * 4];
    float ox = fmaxf(acc.x * sc + b.x, 0.f);
    float oy = fmaxf(acc.y * sc + b.y, 0.f);
    float oz = fmaxf(acc.z * sc + b.z, 0.f);
    float ow = fmaxf(acc.w * sc + b.w, 0.f);
    uint2 st;
    *(__half2*)&st.x = __floats2half2_rn(ox, oy);
    *(__half2*)&st.y = __floats2half2_rn(oz, ow);
    *(uint2*)&g_h1[(size_t)c * 128 + lane * 4] = st;
}

// ---------------- GEMM2 (tf32, fp16 in) + fused alar2 epilogue, fp16 xt2 out ----------------
__global__ __launch_bounds__(256, 2) void k_gemm2(const float* __restrict__ W2,
                                                  const float* __restrict__ att, int n) {
    __shared__ float Hs[32][132];
    __shared__ float Ws2[32][20];
    int tid = threadIdx.x, lane = tid & 31, wid = tid >> 5;
    int m0 = blockIdx.x * 128;
    int wm = wid * 16;

    float acc[2][4];
#pragma unroll
    for (int nt = 0; nt < 2; nt++)
#pragma unroll
        for (int q = 0; q < 4; q++) acc[nt][q] = 0.f;

    int lm = tid & 127;
    int lkq = (tid >> 7) * 16;
    int wkk = tid >> 3, wc = (tid & 7) * 2;

    for (int k0 = 0; k0 < 128; k0 += 32) {
        uint4 hv0 = make_uint4(0, 0, 0, 0), hv1 = hv0;
        if (m0 + lm < n) {
            const __half* hp = &g_h1[(size_t)(m0 + lm) * 128 + k0 + lkq];
            hv0 = *(const uint4*)hp;        // 8 halves
            hv1 = *(const uint4*)(hp + 8);  // 8 halves
        }
        // fp16 -> fp32 is exact; fp16 mantissa <= tf32 mantissa, so no f2tf needed
        {
            const uint32_t* hu = &hv0.x;
#pragma unroll
            for (int j = 0; j < 4; j++) {
                float2 f = __half22float2(*(__half2*)&hu[j]);
                Hs[lkq + j * 2 + 0][lm] = f.x;
                Hs[lkq + j * 2 + 1][lm] = f.y;
            }
            const uint32_t* hu2 = &hv1.x;
#pragma unroll
            for (int j = 0; j < 4; j++) {
                float2 f = __half22float2(*(__half2*)&hu2[j]);
                Hs[lkq + 8 + j * 2 + 0][lm] = f.x;
                Hs[lkq + 8 + j * 2 + 1][lm] = f.y;
            }
        }
        Ws2[wkk][wc]     = f2tf(W2[(size_t)(k0 + wkk) * 16 + wc]);
        Ws2[wkk][wc + 1] = f2tf(W2[(size_t)(k0 + wkk) * 16 + wc + 1]);
        __syncthreads();

#pragma unroll
        for (int kk = 0; kk < 32; kk += 8) {
            int ar = lane >> 2, ak = kk + (lane & 3);
            uint32_t a[4];
            a[0] = __float_as_uint(Hs[ak][wm + ar]);
            a[1] = __float_as_uint(Hs[ak][wm + ar + 8]);
            a[2] = __float_as_uint(Hs[ak + 4][wm + ar]);
            a[3] = __float_as_uint(Hs[ak + 4][wm + ar + 8]);
            uint32_t b0[2], b1[2];
            b0[0] = __float_as_uint(Ws2[ak][ar]);
            b0[1] = __float_as_uint(Ws2[ak + 4][ar]);
            b1[0] = __float_as_uint(Ws2[ak][8 + ar]);
            b1[1] = __float_as_uint(Ws2[ak + 4][8 + ar]);
            mma_tf32(acc[0], a, b0);
            mma_tf32(acc[1], a, b1);
        }
        __syncthreads();
    }

    int ar = lane >> 2, ac = (lane & 3) * 2;
#pragma unroll
    for (int nt = 0; nt < 2; nt++) {
        int r = m0 + wm + ar;
        int c = nt * 8 + ac;
        if (r < n)
            *(__half2*)&g_xt2[(size_t)r * 16 + c] = __floats2half2_rn(acc[nt][0], acc[nt][1]);
        if (r + 8 < n)
            *(__half2*)&g_xt2[(size_t)(r + 8) * 16 + c] = __floats2half2_rn(acc[nt][2], acc[nt][3]);
    }

    // ---- fused alar2 epilogue: row dot with att2 across the 16 cols ----
    float wlv[4], wrv[4];
#pragma unroll
    for (int nt = 0; nt < 2; nt++) {
        int cc = nt * 8 + ac;
        wlv[nt * 2 + 0] = att[cc];
        wlv[nt * 2 + 1] = att[cc + 1];
        wrv[nt * 2 + 0] = att[16 + cc];
        wrv[nt * 2 + 1] = att[16 + cc + 1];
    }
    float alp0 = 0.f, arp0 = 0.f, alp1 = 0.f, arp1 = 0.f;
#pragma unroll
    for (int nt = 0; nt < 2; nt++) {
        alp0 += acc[nt][0] * wlv[nt * 2] + acc[nt][1] * wlv[nt * 2 + 1];
        arp0 += acc[nt][0] * wrv[nt * 2] + acc[nt][1] * wrv[nt * 2 + 1];
        alp1 += acc[nt][2] * wlv[nt * 2] + acc[nt][3] * wlv[nt * 2 + 1];
        arp1 += acc[nt][2] * wrv[nt * 2] + acc[nt][3] * wrv[nt * 2 + 1];
    }
#pragma unroll
    for (int d = 1; d <= 2; d <<= 1) {
        alp0 += __shfl_xor_sync(0xffffffffu, alp0, d);
        arp0 += __shfl_xor_sync(0xffffffffu, arp0, d);
        alp1 += __shfl_xor_sync(0xffffffffu, alp1, d);
        arp1 += __shfl_xor_sync(0xffffffffu, arp1, d);
    }
    if ((lane & 3) == 0) {
        int r = m0 + wm + ar;
        if (r < n)     { g_al2[r] = alp0;     g_ar2[r] = arp0; }
        if (r + 8 < n) { g_al2[r + 8] = alp1; g_ar2[r + 8] = arp1; }
    }
}

// ---------------- single-sweep fused softmax + aggregation layer2 (fp16 gathers) ----------------
__global__ void k_agg2(const float* __restrict__ b2, int n, float* __restrict__ out) {
    __shared__ float sw2[8][32];
    __shared__ int   sr2[8][32];
    int w = (blockIdx.x * blockDim.x + threadIdx.x) >> 5;
    if (w >= n) return;
    int lane = threadIdx.x & 31;
    int wz = (threadIdx.x >> 5) & 7;
    int c = w;
    float dc = g_dinv[c];
    float alc = g_al2[c];
    int beg = g_off[c], end = g_off[c + 1];
    int ch = lane & 15;

    float ps = 0.f, acc = 0.f;
    for (int t0 = beg; t0 < end; t0 += 32) {
        int j = t0 + lane;
        if (j < end) {
            int r = __ldg(&g_adj[j]);
            float e = __expf(lrelu(alc + g_ar2[r]));
            ps += e;
            sw2[wz][lane] = g_dinv[r] * e;
            sr2[wz][lane] = r;
        }
        __syncwarp();
        int cnt = min(32, end - t0);
#pragma unroll 4
        for (int u = 0; u < cnt; u += 2) {
            int uu = u + (lane >> 4);
            if (uu < cnt) {
                int r = sr2[wz][uu];
                acc += sw2[wz][uu] * __half2float(g_xt2[(size_t)r * 16 + ch]);
            }
        }
        __syncwarp();
    }

#pragma unroll
    for (int d = 16; d > 0; d >>= 1)
        ps += __shfl_xor_sync(0xffffffffu, ps, d);
    float se = __expf(lrelu(alc + g_ar2[c]));
    float rs = __fdividef(1.0f, ps + se + 1e-16f);

    acc += __shfl_xor_sync(0xffffffffu, acc, 16);
    acc += dc * se * __half2float(g_xt2[(size_t)c * 16 + ch]);
    if (lane < 16) out[(size_t)c * 16 + ch] = dc * rs * acc + b2[ch];
}

// ---------------- launch ----------------
extern "C" void kernel_launch(void* const* d_in, const int* in_sizes, int n_in,
                              void* d_out, int out_size) {
    const float* x    = (const float*)d_in[0];
    const int*   ei   = (const int*)d_in[1];
    const float* W1   = (const float*)d_in[2];
    const float* att1 = (const float*)d_in[3];
    const float* b1   = (const float*)d_in[4];
    const float* W2   = (const float*)d_in[5];
    const float* att2 = (const float*)d_in[6];
    const float* b2   = (const float*)d_in[7];
    float* out = (float*)d_out;

    int n = in_sizes[0] / 256;
    int e = in_sizes[1] / 2;
    int nb = (n + 1023) / 1024;

    const int T = 256;
    k_init<<<(n + T - 1) / T, T>>>(n);
    k_deg_count<<<(e + T - 1) / T, T>>>(ei, e);
    k_dinv<<<(n + T - 1) / T, T>>>(n);
    k_scan_blocks<<<nb, 1024>>>(n);
    k_scan_tops<<<1, 128>>>(nb);
    k_scan_add<<<nb, 1024>>>(n, e);
    k_scatter<<<(e + T - 1) / T, T>>>(ei, e);

    k_gemm1<<<(n + 127) / 128, 256>>>(x, W1, att1, n);
    k_agg1<<<(n * 32 + 255) / 256, 256>>>(b1, n);

    k_gemm2<<<(n + 127) / 128, 256>>>(W2, att2, n);
    k_agg2<<<(n * 32 + 255) / 256, 256>>>(b2, n, out);
}

// round 9
// speedup vs baseline: 3.5599x; 1.0657x over previous
#include <cuda_runtime.h>
#include <cuda_fp16.h>
#include <math.h>
#include <stdint.h>

#define NN 100000
#define EE 1600000
#define NB_SCAN ((NN + 1023) / 1024)

// ---------------- scratch (static device globals) ----------------
__device__ float    g_deg[NN];
__device__ float    g_dinv[NN];
__device__ __half   g_xt1[(size_t)NN * 128];
__device__ float    g_al1[NN * 4];
__device__ float    g_ar1[NN * 4];
__device__ __half   g_h1[(size_t)NN * 128];
__device__ __half   g_xt2[NN * 16];
__device__ float    g_al2[NN];
__device__ float    g_ar2[NN];
// CSR by destination (col)
__device__ int      g_cnt[NN];
__device__ int      g_off[NN + 1];
__device__ int      g_wpos[NN];
__device__ int      g_bsum[NB_SCAN + 1];
__device__ int      g_adj[EE];     // source row only

__device__ __forceinline__ float lrelu(float a) { return a >= 0.f ? a : 0.2f * a; }

__device__ __forceinline__ float f2tf(float f) {
    uint32_t u;
    asm("cvt.rna.tf32.f32 %0, %1;" : "=r"(u) : "f"(f));
    return __uint_as_float(u);
}
__device__ __forceinline__ uint32_t f2tfu(float f) {
    uint32_t u;
    asm("cvt.rna.tf32.f32 %0, %1;" : "=r"(u) : "f"(f));
    return u;
}

__device__ __forceinline__ void mma_tf32(float* c, const uint32_t* a, const uint32_t* b) {
    asm volatile(
        "mma.sync.aligned.m16n8k8.row.col.f32.tf32.tf32.f32 "
        "{%0,%1,%2,%3}, {%4,%5,%6,%7}, {%8,%9}, {%0,%1,%2,%3};"
        : "+f"(c[0]), "+f"(c[1]), "+f"(c[2]), "+f"(c[3])
        : "r"(a[0]), "r"(a[1]), "r"(a[2]), "r"(a[3]), "r"(b[0]), "r"(b[1]));
}

__device__ __forceinline__ void cp16(uint32_t d, const void* s, int sz) {
    asm volatile("cp.async.ca.shared.global [%0], [%1], 16, %2;"
                 :: "r"(d), "l"(s), "r"(sz));
}
__device__ __forceinline__ void cp_commit() {
    asm volatile("cp.async.commit_group;" ::: "memory");
}

// ---------------- init ----------------
__global__ void k_init(int n) {
    int i = blockIdx.x * blockDim.x + threadIdx.x;
    if (i < n) { g_deg[i] = 1.0f; g_cnt[i] = 0; }
}

__global__ void k_deg_count(const int* __restrict__ ei, int e) {
    int i = blockIdx.x * blockDim.x + threadIdx.x;
    if (i < e) {
        atomicAdd(&g_deg[ei[i]], 1.0f);
        atomicAdd(&g_cnt[ei[e + i]], 1);
    }
}

// ---------------- multi-block exclusive scan over g_cnt (+ fused dinv) ----------------
__global__ void k_scan_blocks(int n) {
    __shared__ int warpsums[32];
    int i = blockIdx.x * 1024 + threadIdx.x;
    int lane = threadIdx.x & 31, wid = threadIdx.x >> 5;
    if (i < n) g_dinv[i] = rsqrtf(g_deg[i]);   // fused dinv
    int v = (i < n) ? g_cnt[i] : 0;
    int s = v;
#pragma unroll
    for (int d = 1; d < 32; d <<= 1) {
        int t = __shfl_up_sync(0xffffffffu, s, d);
        if (lane >= d) s += t;
    }
    if (lane == 31) warpsums[wid] = s;
    __syncthreads();
    if (wid == 0) {
        int ws = warpsums[lane];
#pragma unroll
        for (int d = 1; d < 32; d <<= 1) {
            int t = __shfl_up_sync(0xffffffffu, ws, d);
            if (lane >= d) ws += t;
        }
        warpsums[lane] = ws;
    }
    __syncthreads();
    int base = (wid > 0) ? warpsums[wid - 1] : 0;
    int exc = s - v + base;
    if (i < n) g_off[i] = exc;
    if (threadIdx.x == 1023) g_bsum[blockIdx.x] = exc + v;
}

__global__ void k_scan_tops(int nb) {
    __shared__ int warpsums[4];
    int lane = threadIdx.x & 31, wid = threadIdx.x >> 5;
    int v = (threadIdx.x < nb) ? g_bsum[threadIdx.x] : 0;
    int s = v;
#pragma unroll
    for (int d = 1; d < 32; d <<= 1) {
        int t = __shfl_up_sync(0xffffffffu, s, d);
        if (lane >= d) s += t;
    }
    if (lane == 31) warpsums[wid] = s;
    __syncthreads();
    int base = 0;
#pragma unroll
    for (int w = 0; w < 4; w++) if (w < wid) base += warpsums[w];
    if (threadIdx.x < nb) g_bsum[threadIdx.x] = s - v + base;
}

__global__ void k_scan_add(int n, int e) {
    int i = blockIdx.x * 1024 + threadIdx.x;
    if (i < n) {
        int o = g_off[i] + g_bsum[blockIdx.x];
        g_off[i] = o;
        g_wpos[i] = o;
    }
    if (i == 0) g_off[n] = e;
}

__global__ void k_scatter(const int* __restrict__ ei, int e) {
    int i = blockIdx.x * blockDim.x + threadIdx.x;
    if (i >= e) return;
    int r = ei[i], c = ei[e + i];
    int p = atomicAdd(&g_wpos[c], 1);
    g_adj[p] = r;
}

// ---------------- GEMM1 (tf32, cp.async double-buffered, RNA cvt on fragments) ----------------
__global__ __launch_bounds__(256, 2) void k_gemm1(const float* __restrict__ X,
                                                  const float* __restrict__ W,
                                                  const float* __restrict__ att, int n) {
    __shared__ __align__(16) float Xs[2][128][20];   // [m][k] + pad4
    __shared__ __align__(16) float Ws[2][16][132];   // [k][n] + pad4
    int tid = threadIdx.x, lane = tid & 31, wid = tid >> 5;
    int m0 = blockIdx.x * 128;
    int wm = (wid & 1) * 64, wn = (wid >> 1) * 32;

    float acc[4][4][4];
#pragma unroll
    for (int mt = 0; mt < 4; mt++)
#pragma unroll
        for (int nt = 0; nt < 4; nt++)
#pragma unroll
            for (int q = 0; q < 4; q++) acc[mt][nt][q] = 0.f;

    int lm = tid & 127;
    int lkq = (tid >> 7) * 8;
    int wk = tid >> 4;
    int wq = (tid & 15) * 8;

    bool mok = (m0 + lm < n);
    int xsz = mok ? 16 : 0;
    const float* xsrc = X + (size_t)(m0 + lm) * 256 + lkq;
    const float* wsrc = W + (size_t)wk * 128 + wq;
    uint32_t xd = (uint32_t)__cvta_generic_to_shared(&Xs[0][lm][lkq]);
    uint32_t wd = (uint32_t)__cvta_generic_to_shared(&Ws[0][wk][wq]);
    const uint32_t XST = sizeof(float) * 128 * 20;
    const uint32_t WST = sizeof(float) * 16 * 132;

    cp16(xd, xsrc, xsz);
    cp16(xd + 16, xsrc + 4, xsz);
    cp16(wd, wsrc, 16);
    cp16(wd + 16, wsrc + 4, 16);
    cp_commit();

#pragma unroll 1
    for (int t = 0; t < 16; t++) {
        int s = t & 1;
        if (t + 1 < 16) {
            int s1 = (t + 1) & 1;
            int k0 = (t + 1) * 16;
            cp16(xd + s1 * XST, xsrc + k0, xsz);
            cp16(xd + s1 * XST + 16, xsrc + k0 + 4, xsz);
            cp16(wd + s1 * WST, wsrc + (size_t)k0 * 128, 16);
            cp16(wd + s1 * WST + 16, wsrc + (size_t)k0 * 128 + 4, 16);
            cp_commit();
            asm volatile("cp.async.wait_group 1;" ::: "memory");
        } else {
            asm volatile("cp.async.wait_group 0;" ::: "memory");
        }
        __syncthreads();

#pragma unroll
        for (int kk = 0; kk < 16; kk += 8) {
            int ar = lane >> 2, ak = kk + (lane & 3);
            uint32_t a[4][4], b[4][2];
#pragma unroll
            for (int mt = 0; mt < 4; mt++) {
                int r = wm + mt * 16 + ar;
                a[mt][0] = f2tfu(Xs[s][r][ak]);
                a[mt][1] = f2tfu(Xs[s][r + 8][ak]);
                a[mt][2] = f2tfu(Xs[s][r][ak + 4]);
                a[mt][3] = f2tfu(Xs[s][r + 8][ak + 4]);
            }
#pragma unroll
            for (int nt = 0; nt < 4; nt++) {
                int c = wn + nt * 8 + ar;
                b[nt][0] = f2tfu(Ws[s][ak][c]);
                b[nt][1] = f2tfu(Ws[s][ak + 4][c]);
            }
#pragma unroll
            for (int mt = 0; mt < 4; mt++)
#pragma unroll
                for (int nt = 0; nt < 4; nt++)
                    mma_tf32(acc[mt][nt], a[mt], b[nt]);
        }
        __syncthreads();
    }

    int ar = lane >> 2, ac = (lane & 3) * 2;
#pragma unroll
    for (int mt = 0; mt < 4; mt++) {
        int r = m0 + wm + mt * 16 + ar;
#pragma unroll
        for (int nt = 0; nt < 4; nt++) {
            int c = wn + nt * 8 + ac;
            if (r < n)
                *(__half2*)&g_xt1[(size_t)r * 128 + c] =
                    __floats2half2_rn(acc[mt][nt][0], acc[mt][nt][1]);
            if (r + 8 < n)
                *(__half2*)&g_xt1[(size_t)(r + 8) * 128 + c] =
                    __floats2half2_rn(acc[mt][nt][2], acc[mt][nt][3]);
        }
    }

    // ---- fused alar1 epilogue ----
    int hh = wid >> 1;
    float wlv[8], wrv[8];
#pragma unroll
    for (int nt = 0; nt < 4; nt++) {
        int cc = nt * 8 + ac;
        wlv[nt * 2 + 0] = att[hh * 64 + cc];
        wlv[nt * 2 + 1] = att[hh * 64 + cc + 1];
        wrv[nt * 2 + 0] = att[hh * 64 + 32 + cc];
        wrv[nt * 2 + 1] = att[hh * 64 + 32 + cc + 1];
    }
#pragma unroll
    for (int mt = 0; mt < 4; mt++) {
        float alp0 = 0.f, arp0 = 0.f, alp1 = 0.f, arp1 = 0.f;
#pragma unroll
        for (int nt = 0; nt < 4; nt++) {
            alp0 += acc[mt][nt][0] * wlv[nt * 2] + acc[mt][nt][1] * wlv[nt * 2 + 1];
            arp0 += acc[mt][nt][0] * wrv[nt * 2] + acc[mt][nt][1] * wrv[nt * 2 + 1];
            alp1 += acc[mt][nt][2] * wlv[nt * 2] + acc[mt][nt][3] * wlv[nt * 2 + 1];
            arp1 += acc[mt][nt][2] * wrv[nt * 2] + acc[mt][nt][3] * wrv[nt * 2 + 1];
        }
#pragma unroll
        for (int d = 1; d <= 2; d <<= 1) {
            alp0 += __shfl_xor_sync(0xffffffffu, alp0, d);
            arp0 += __shfl_xor_sync(0xffffffffu, arp0, d);
            alp1 += __shfl_xor_sync(0xffffffffu, alp1, d);
            arp1 += __shfl_xor_sync(0xffffffffu, arp1, d);
        }
        if ((lane & 3) == 0) {
            int r = m0 + wm + mt * 16 + ar;
            if (r < n)     { g_al1[r * 4 + hh] = alp0;       g_ar1[r * 4 + hh] = arp0; }
            if (r + 8 < n) { g_al1[(r + 8) * 4 + hh] = alp1; g_ar1[(r + 8) * 4 + hh] = arp1; }
        }
    }
}

// ---------------- single-sweep fused softmax + aggregation layer1 (fp16 gathers) ----------------
__global__ void k_agg1(const float* __restrict__ b1, int n) {
    __shared__ float sw[8][32][4];
    __shared__ int   sr[8][32];
    int w = (blockIdx.x * blockDim.x + threadIdx.x) >> 5;
    if (w >= n) return;
    int lane = threadIdx.x & 31;
    int wz = (threadIdx.x >> 5) & 7;
    int c = w;
    float dc = g_dinv[c];
    float4 alc = *(const float4*)&g_al1[c * 4];
    float4 arc = *(const float4*)&g_ar1[c * 4];
    int beg = g_off[c], end = g_off[c + 1];
    int h = lane >> 3;

    float4 ps = make_float4(0.f, 0.f, 0.f, 0.f);
    float4 acc = make_float4(0.f, 0.f, 0.f, 0.f);

    for (int t0 = beg; t0 < end; t0 += 32) {
        int j = t0 + lane;
        if (j < end) {
            int r = __ldg(&g_adj[j]);
            float4 ar4 = *(const float4*)&g_ar1[r * 4];
            float di = g_dinv[r];
            float e0 = __expf(lrelu(alc.x + ar4.x));
            float e1 = __expf(lrelu(alc.y + ar4.y));
            float e2 = __expf(lrelu(alc.z + ar4.z));
            float e3 = __expf(lrelu(alc.w + ar4.w));
            ps.x += e0; ps.y += e1; ps.z += e2; ps.w += e3;
            sw[wz][lane][0] = di * e0;
            sw[wz][lane][1] = di * e1;
            sw[wz][lane][2] = di * e2;
            sw[wz][lane][3] = di * e3;
            sr[wz][lane] = r;
        }
        __syncwarp();
        int cnt = min(32, end - t0);
#pragma unroll 4
        for (int u = 0; u < cnt; u++) {
            int r = sr[wz][u];
            float wh = sw[wz][u][h];
            uint2 u2 = *(const uint2*)&g_xt1[(size_t)r * 128 + lane * 4];
            float2 f0 = __half22float2(*(__half2*)&u2.x);
            float2 f1 = __half22float2(*(__half2*)&u2.y);
            acc.x += wh * f0.x; acc.y += wh * f0.y;
            acc.z += wh * f1.x; acc.w += wh * f1.y;
        }
        __syncwarp();
    }

#pragma unroll
    for (int d = 16; d > 0; d >>= 1) {
        ps.x += __shfl_xor_sync(0xffffffffu, ps.x, d);
        ps.y += __shfl_xor_sync(0xffffffffu, ps.y, d);
        ps.z += __shfl_xor_sync(0xffffffffu, ps.z, d);
        ps.w += __shfl_xor_sync(0xffffffffu, ps.w, d);
    }
    float se0 = __expf(lrelu(alc.x + arc.x));
    float se1 = __expf(lrelu(alc.y + arc.y));
    float se2 = __expf(lrelu(alc.z + arc.z));
    float se3 = __expf(lrelu(alc.w + arc.w));
    float rs0 = __fdividef(1.0f, ps.x + se0 + 1e-16f);
    float rs1 = __fdividef(1.0f, ps.y + se1 + 1e-16f);
    float rs2 = __fdividef(1.0f, ps.z + se2 + 1e-16f);
    float rs3 = __fdividef(1.0f, ps.w + se3 + 1e-16f);
    float seh = h < 2 ? (h == 0 ? se0 : se1) : (h == 2 ? se2 : se3);
    float rsh = h < 2 ? (h == 0 ? rs0 : rs1) : (h == 2 ? rs2 : rs3);

    uint2 uc = *(const uint2*)&g_xt1[(size_t)c * 128 + lane * 4];
    float2 c0 = __half22float2(*(__half2*)&uc.x);
    float2 c1 = __half22float2(*(__half2*)&uc.y);
    float wself = dc * seh;
    acc.x += wself * c0.x; acc.y += wself * c0.y;
    acc.z += wself * c1.x; acc.w += wself * c1.y;
    float sc = dc * rsh;

    float4 b = *(const float4*)&b1[lane * 4];
    float ox = fmaxf(acc.x * sc + b.x, 0.f);
    float oy = fmaxf(acc.y * sc + b.y, 0.f);
    float oz = fmaxf(acc.z * sc + b.z, 0.f);
    float ow = fmaxf(acc.w * sc + b.w, 0.f);
    uint2 st;
    *(__half2*)&st.x = __floats2half2_rn(ox, oy);
    *(__half2*)&st.y = __floats2half2_rn(oz, ow);
    *(uint2*)&g_h1[(size_t)c * 128 + lane * 4] = st;
}

// ---------------- GEMM2 (tf32, fp16 in) + fused alar2 epilogue, fp16 xt2 out ----------------
__global__ __launch_bounds__(256, 2) void k_gemm2(const float* __restrict__ W2,
                                                  const float* __restrict__ att, int n) {
    __shared__ float Hs[32][132];
    __shared__ float Ws2[32][20];
    int tid = threadIdx.x, lane = tid & 31, wid = tid >> 5;
    int m0 = blockIdx.x * 128;
    int wm = wid * 16;

    float acc[2][4];
#pragma unroll
    for (int nt = 0; nt < 2; nt++)
#pragma unroll
        for (int q = 0; q < 4; q++) acc[nt][q] = 0.f;

    int lm = tid & 127;
    int lkq = (tid >> 7) * 16;
    int wkk = tid >> 3, wc = (tid & 7) * 2;

    for (int k0 = 0; k0 < 128; k0 += 32) {
        uint4 hv0 = make_uint4(0, 0, 0, 0), hv1 = hv0;
        if (m0 + lm < n) {
            const __half* hp = &g_h1[(size_t)(m0 + lm) * 128 + k0 + lkq];
            hv0 = *(const uint4*)hp;
            hv1 = *(const uint4*)(hp + 8);
        }
        {
            const uint32_t* hu = &hv0.x;
#pragma unroll
            for (int j = 0; j < 4; j++) {
                float2 f = __half22float2(*(__half2*)&hu[j]);
                Hs[lkq + j * 2 + 0][lm] = f.x;
                Hs[lkq + j * 2 + 1][lm] = f.y;
            }
            const uint32_t* hu2 = &hv1.x;
#pragma unroll
            for (int j = 0; j < 4; j++) {
                float2 f = __half22float2(*(__half2*)&hu2[j]);
                Hs[lkq + 8 + j * 2 + 0][lm] = f.x;
                Hs[lkq + 8 + j * 2 + 1][lm] = f.y;
            }
        }
        Ws2[wkk][wc]     = f2tf(W2[(size_t)(k0 + wkk) * 16 + wc]);
        Ws2[wkk][wc + 1] = f2tf(W2[(size_t)(k0 + wkk) * 16 + wc + 1]);
        __syncthreads();

#pragma unroll
        for (int kk = 0; kk < 32; kk += 8) {
            int ar = lane >> 2, ak = kk + (lane & 3);
            uint32_t a[4];
            a[0] = __float_as_uint(Hs[ak][wm + ar]);
            a[1] = __float_as_uint(Hs[ak][wm + ar + 8]);
            a[2] = __float_as_uint(Hs[ak + 4][wm + ar]);
            a[3] = __float_as_uint(Hs[ak + 4][wm + ar + 8]);
            uint32_t b0[2], b1[2];
            b0[0] = __float_as_uint(Ws2[ak][ar]);
            b0[1] = __float_as_uint(Ws2[ak + 4][ar]);
            b1[0] = __float_as_uint(Ws2[ak][8 + ar]);
            b1[1] = __float_as_uint(Ws2[ak + 4][8 + ar]);
            mma_tf32(acc[0], a, b0);
            mma_tf32(acc[1], a, b1);
        }
        __syncthreads();
    }

    int ar = lane >> 2, ac = (lane & 3) * 2;
#pragma unroll
    for (int nt = 0; nt < 2; nt++) {
        int r = m0 + wm + ar;
        int c = nt * 8 + ac;
        if (r < n)
            *(__half2*)&g_xt2[(size_t)r * 16 + c] = __floats2half2_rn(acc[nt][0], acc[nt][1]);
        if (r + 8 < n)
            *(__half2*)&g_xt2[(size_t)(r + 8) * 16 + c] = __floats2half2_rn(acc[nt][2], acc[nt][3]);
    }

    // ---- fused alar2 epilogue ----
    float wlv[4], wrv[4];
#pragma unroll
    for (int nt = 0; nt < 2; nt++) {
        int cc = nt * 8 + ac;
        wlv[nt * 2 + 0] = att[cc];
        wlv[nt * 2 + 1] = att[cc + 1];
        wrv[nt * 2 + 0] = att[16 + cc];
        wrv[nt * 2 + 1] = att[16 + cc + 1];
    }
    float alp0 = 0.f, arp0 = 0.f, alp1 = 0.f, arp1 = 0.f;
#pragma unroll
    for (int nt = 0; nt < 2; nt++) {
        alp0 += acc[nt][0] * wlv[nt * 2] + acc[nt][1] * wlv[nt * 2 + 1];
        arp0 += acc[nt][0] * wrv[nt * 2] + acc[nt][1] * wrv[nt * 2 + 1];
        alp1 += acc[nt][2] * wlv[nt * 2] + acc[nt][3] * wlv[nt * 2 + 1];
        arp1 += acc[nt][2] * wrv[nt * 2] + acc[nt][3] * wrv[nt * 2 + 1];
    }
#pragma unroll
    for (int d = 1; d <= 2; d <<= 1) {
        alp0 += __shfl_xor_sync(0xffffffffu, alp0, d);
        arp0 += __shfl_xor_sync(0xffffffffu, arp0, d);
        alp1 += __shfl_xor_sync(0xffffffffu, alp1, d);
        arp1 += __shfl_xor_sync(0xffffffffu, arp1, d);
    }
    if ((lane & 3) == 0) {
        int r = m0 + wm + ar;
        if (r < n)     { g_al2[r] = alp0;     g_ar2[r] = arp0; }
        if (r + 8 < n) { g_al2[r + 8] = alp1; g_ar2[r + 8] = arp1; }
    }
}

// ---------------- layer2 agg: half-warp per node, shfl staging ----------------
__global__ void k_agg2(const float* __restrict__ b2, int n, float* __restrict__ out) {
    int hw = (blockIdx.x * blockDim.x + threadIdx.x) >> 4;   // half-warp = node
    int sub = threadIdx.x & 15;
    unsigned hm = 0xFFFFu << (threadIdx.x & 16);
    bool valid = hw < n;
    int c = valid ? hw : (n - 1);
    float dc = g_dinv[c];
    float alc = g_al2[c];
    int beg = g_off[c], end = g_off[c + 1];

    float ps = 0.f, acc = 0.f;
    for (int t0 = beg; t0 < end; t0 += 16) {
        int j = t0 + sub;
        int r = 0; float wv = 0.f;
        if (j < end) {
            r = __ldg(&g_adj[j]);
            float e = __expf(lrelu(alc + g_ar2[r]));
            ps += e;
            wv = g_dinv[r] * e;
        }
        int cnt = min(16, end - t0);
        for (int u = 0; u < cnt; u++) {
            int ru = __shfl_sync(hm, r, u, 16);
            float wu = __shfl_sync(hm, wv, u, 16);
            acc += wu * __half2float(g_xt2[(size_t)ru * 16 + sub]);
        }
    }
#pragma unroll
    for (int d = 8; d > 0; d >>= 1)
        ps += __shfl_xor_sync(hm, ps, d, 16);
    float se = __expf(lrelu(alc + g_ar2[c]));
    float rs = __fdividef(1.0f, ps + se + 1e-16f);
    acc += dc * se * __half2float(g_xt2[(size_t)c * 16 + sub]);
    if (valid) out[(size_t)c * 16 + sub] = dc * rs * acc + b2[sub];
}

// ---------------- launch ----------------
extern "C" void kernel_launch(void* const* d_in, const int* in_sizes, int n_in,
                              void* d_out, int out_size) {
    const float* x    = (const float*)d_in[0];
    const int*   ei   = (const int*)d_in[1];
    const float* W1   = (const float*)d_in[2];
    const float* att1 = (const float*)d_in[3];
    const float* b1   = (const float*)d_in[4];
    const float* W2   = (const float*)d_in[5];
    const float* att2 = (const float*)d_in[6];
    const float* b2   = (const float*)d_in[7];
    float* out = (float*)d_out;

    int n = in_sizes[0] / 256;
    int e = in_sizes[1] / 2;
    int nb = (n + 1023) / 1024;

    const int T = 256;
    k_init<<<(n + T - 1) / T, T>>>(n);
    k_deg_count<<<(e + T - 1) / T, T>>>(ei, e);
    k_scan_blocks<<<nb, 1024>>>(n);
    k_scan_tops<<<1, 128>>>(nb);
    k_scan_add<<<nb, 1024>>>(n, e);
    k_scatter<<<(e + T - 1) / T, T>>>(ei, e);

    k_gemm1<<<(n + 127) / 128, 256>>>(x, W1, att1, n);
    k_agg1<<<(n * 32 + 255) / 256, 256>>>(b1, n);

    k_gemm2<<<(n + 127) / 128, 256>>>(W2, att2, n);
    k_agg2<<<(n * 16 + 255) / 256, 256>>>(b2, n, out);
}

// round 10
// speedup vs baseline: 3.8503x; 1.0816x over previous
#include <cuda_runtime.h>
#include <cuda_fp16.h>
#include <math.h>
#include <stdint.h>

#define NN 100000
#define EE 1600000
#define NB_SCAN ((NN + 1023) / 1024)

// ---------------- scratch (static device globals) ----------------
__device__ float    g_deg[NN];
__device__ float    g_dinv[NN];
__device__ __half   g_xt1[(size_t)NN * 128];
__device__ float    g_al1[NN * 4];
__device__ float    g_ar1[NN * 4];
__device__ __half   g_h1[(size_t)NN * 128];
__device__ __half   g_xt2[NN * 16];
__device__ float    g_al2[NN];
__device__ float    g_ar2[NN];
// CSR by destination (col)
__device__ int      g_cnt[NN];
__device__ int      g_off[NN + 1];
__device__ int      g_wpos[NN];
__device__ int      g_bsum[NB_SCAN + 1];
__device__ int      g_adj[EE];     // source row only

__device__ __forceinline__ float lrelu(float a) { return a >= 0.f ? a : 0.2f * a; }

__device__ __forceinline__ float f2tf(float f) {
    uint32_t u;
    asm("cvt.rna.tf32.f32 %0, %1;" : "=r"(u) : "f"(f));
    return __uint_as_float(u);
}
__device__ __forceinline__ uint32_t f2tfu(float f) {
    uint32_t u;
    asm("cvt.rna.tf32.f32 %0, %1;" : "=r"(u) : "f"(f));
    return u;
}

__device__ __forceinline__ void mma_tf32(float* c, const uint32_t* a, const uint32_t* b) {
    asm volatile(
        "mma.sync.aligned.m16n8k8.row.col.f32.tf32.tf32.f32 "
        "{%0,%1,%2,%3}, {%4,%5,%6,%7}, {%8,%9}, {%0,%1,%2,%3};"
        : "+f"(c[0]), "+f"(c[1]), "+f"(c[2]), "+f"(c[3])
        : "r"(a[0]), "r"(a[1]), "r"(a[2]), "r"(a[3]), "r"(b[0]), "r"(b[1]));
}

__device__ __forceinline__ void cp16(uint32_t d, const void* s, int sz) {
    asm volatile("cp.async.ca.shared.global [%0], [%1], 16, %2;"
                 :: "r"(d), "l"(s), "r"(sz));
}
__device__ __forceinline__ void cp_commit() {
    asm volatile("cp.async.commit_group;" ::: "memory");
}

// ---------------- init ----------------
__global__ void k_init(int n) {
    int i = blockIdx.x * blockDim.x + threadIdx.x;
    if (i < n) { g_deg[i] = 1.0f; g_cnt[i] = 0; }
}

__global__ void k_deg_count(const int* __restrict__ ei, int e) {
    int i = blockIdx.x * blockDim.x + threadIdx.x;
    if (i < e) {
        atomicAdd(&g_deg[ei[i]], 1.0f);
        atomicAdd(&g_cnt[ei[e + i]], 1);
    }
}

// ---------------- multi-block exclusive scan over g_cnt (+ fused dinv) ----------------
__global__ void k_scan_blocks(int n) {
    __shared__ int warpsums[32];
    int i = blockIdx.x * 1024 + threadIdx.x;
    int lane = threadIdx.x & 31, wid = threadIdx.x >> 5;
    if (i < n) g_dinv[i] = rsqrtf(g_deg[i]);   // fused dinv
    int v = (i < n) ? g_cnt[i] : 0;
    int s = v;
#pragma unroll
    for (int d = 1; d < 32; d <<= 1) {
        int t = __shfl_up_sync(0xffffffffu, s, d);
        if (lane >= d) s += t;
    }
    if (lane == 31) warpsums[wid] = s;
    __syncthreads();
    if (wid == 0) {
        int ws = warpsums[lane];
#pragma unroll
        for (int d = 1; d < 32; d <<= 1) {
            int t = __shfl_up_sync(0xffffffffu, ws, d);
            if (lane >= d) ws += t;
        }
        warpsums[lane] = ws;
    }
    __syncthreads();
    int base = (wid > 0) ? warpsums[wid - 1] : 0;
    int exc = s - v + base;
    if (i < n) g_off[i] = exc;
    if (threadIdx.x == 1023) g_bsum[blockIdx.x] = exc + v;  // raw block total
}

// scan_add computes its own block base from raw totals (replaces scan_tops)
__global__ void k_scan_add(int n, int e) {
    __shared__ int sbase;
    if (threadIdx.x == 0) sbase = 0;
    __syncthreads();
    if (threadIdx.x < blockIdx.x) atomicAdd(&sbase, g_bsum[threadIdx.x]);
    __syncthreads();
    int i = blockIdx.x * 1024 + threadIdx.x;
    if (i < n) {
        int o = g_off[i] + sbase;
        g_off[i] = o;
        g_wpos[i] = o;
    }
    if (i == 0) g_off[n] = e;
}

__global__ void k_scatter(const int* __restrict__ ei, int e) {
    int i = blockIdx.x * blockDim.x + threadIdx.x;
    if (i >= e) return;
    int r = ei[i], c = ei[e + i];
    int p = atomicAdd(&g_wpos[c], 1);
    g_adj[p] = r;
}

// ---------------- GEMM1 (tf32, cp.async double-buffered, RNA cvt on fragments) ----------------
__global__ __launch_bounds__(256, 2) void k_gemm1(const float* __restrict__ X,
                                                  const float* __restrict__ W,
                                                  const float* __restrict__ att, int n) {
    __shared__ __align__(16) float Xs[2][128][20];   // [m][k] + pad4
    __shared__ __align__(16) float Ws[2][16][132];   // [k][n] + pad4
    int tid = threadIdx.x, lane = tid & 31, wid = tid >> 5;
    int m0 = blockIdx.x * 128;
    int wm = (wid & 1) * 64, wn = (wid >> 1) * 32;

    float acc[4][4][4];
#pragma unroll
    for (int mt = 0; mt < 4; mt++)
#pragma unroll
        for (int nt = 0; nt < 4; nt++)
#pragma unroll
            for (int q = 0; q < 4; q++) acc[mt][nt][q] = 0.f;

    int lm = tid & 127;
    int lkq = (tid >> 7) * 8;
    int wk = tid >> 4;
    int wq = (tid & 15) * 8;

    bool mok = (m0 + lm < n);
    int xsz = mok ? 16 : 0;
    const float* xsrc = X + (size_t)(m0 + lm) * 256 + lkq;
    const float* wsrc = W + (size_t)wk * 128 + wq;
    uint32_t xd = (uint32_t)__cvta_generic_to_shared(&Xs[0][lm][lkq]);
    uint32_t wd = (uint32_t)__cvta_generic_to_shared(&Ws[0][wk][wq]);
    const uint32_t XST = sizeof(float) * 128 * 20;
    const uint32_t WST = sizeof(float) * 16 * 132;

    cp16(xd, xsrc, xsz);
    cp16(xd + 16, xsrc + 4, xsz);
    cp16(wd, wsrc, 16);
    cp16(wd + 16, wsrc + 4, 16);
    cp_commit();

#pragma unroll 1
    for (int t = 0; t < 16; t++) {
        int s = t & 1;
        if (t + 1 < 16) {
            int s1 = (t + 1) & 1;
            int k0 = (t + 1) * 16;
            cp16(xd + s1 * XST, xsrc + k0, xsz);
            cp16(xd + s1 * XST + 16, xsrc + k0 + 4, xsz);
            cp16(wd + s1 * WST, wsrc + (size_t)k0 * 128, 16);
            cp16(wd + s1 * WST + 16, wsrc + (size_t)k0 * 128 + 4, 16);
            cp_commit();
            asm volatile("cp.async.wait_group 1;" ::: "memory");
        } else {
            asm volatile("cp.async.wait_group 0;" ::: "memory");
        }
        __syncthreads();

#pragma unroll
        for (int kk = 0; kk < 16; kk += 8) {
            int ar = lane >> 2, ak = kk + (lane & 3);
            uint32_t a[4][4], b[4][2];
#pragma unroll
            for (int mt = 0; mt < 4; mt++) {
                int r = wm + mt * 16 + ar;
                a[mt][0] = f2tfu(Xs[s][r][ak]);
                a[mt][1] = f2tfu(Xs[s][r + 8][ak]);
                a[mt][2] = f2tfu(Xs[s][r][ak + 4]);
                a[mt][3] = f2tfu(Xs[s][r + 8][ak + 4]);
            }
#pragma unroll
            for (int nt = 0; nt < 4; nt++) {
                int c = wn + nt * 8 + ar;
                b[nt][0] = f2tfu(Ws[s][ak][c]);
                b[nt][1] = f2tfu(Ws[s][ak + 4][c]);
            }
#pragma unroll
            for (int mt = 0; mt < 4; mt++)
#pragma unroll
                for (int nt = 0; nt < 4; nt++)
                    mma_tf32(acc[mt][nt], a[mt], b[nt]);
        }
        __syncthreads();
    }

    int ar = lane >> 2, ac = (lane & 3) * 2;
#pragma unroll
    for (int mt = 0; mt < 4; mt++) {
        int r = m0 + wm + mt * 16 + ar;
#pragma unroll
        for (int nt = 0; nt < 4; nt++) {
            int c = wn + nt * 8 + ac;
            if (r < n)
                *(__half2*)&g_xt1[(size_t)r * 128 + c] =
                    __floats2half2_rn(acc[mt][nt][0], acc[mt][nt][1]);
            if (r + 8 < n)
                *(__half2*)&g_xt1[(size_t)(r + 8) * 128 + c] =
                    __floats2half2_rn(acc[mt][nt][2], acc[mt][nt][3]);
        }
    }

    // ---- fused alar1 epilogue ----
    int hh = wid >> 1;
    float wlv[8], wrv[8];
#pragma unroll
    for (int nt = 0; nt < 4; nt++) {
        int cc = nt * 8 + ac;
        wlv[nt * 2 + 0] = att[hh * 64 + cc];
        wlv[nt * 2 + 1] = att[hh * 64 + cc + 1];
        wrv[nt * 2 + 0] = att[hh * 64 + 32 + cc];
        wrv[nt * 2 + 1] = att[hh * 64 + 32 + cc + 1];
    }
#pragma unroll
    for (int mt = 0; mt < 4; mt++) {
        float alp0 = 0.f, arp0 = 0.f, alp1 = 0.f, arp1 = 0.f;
#pragma unroll
        for (int nt = 0; nt < 4; nt++) {
            alp0 += acc[mt][nt][0] * wlv[nt * 2] + acc[mt][nt][1] * wlv[nt * 2 + 1];
            arp0 += acc[mt][nt][0] * wrv[nt * 2] + acc[mt][nt][1] * wrv[nt * 2 + 1];
            alp1 += acc[mt][nt][2] * wlv[nt * 2] + acc[mt][nt][3] * wlv[nt * 2 + 1];
            arp1 += acc[mt][nt][2] * wrv[nt * 2] + acc[mt][nt][3] * wrv[nt * 2 + 1];
        }
#pragma unroll
        for (int d = 1; d <= 2; d <<= 1) {
            alp0 += __shfl_xor_sync(0xffffffffu, alp0, d);
            arp0 += __shfl_xor_sync(0xffffffffu, arp0, d);
            alp1 += __shfl_xor_sync(0xffffffffu, alp1, d);
            arp1 += __shfl_xor_sync(0xffffffffu, arp1, d);
        }
        if ((lane & 3) == 0) {
            int r = m0 + wm + mt * 16 + ar;
            if (r < n)     { g_al1[r * 4 + hh] = alp0;       g_ar1[r * 4 + hh] = arp0; }
            if (r + 8 < n) { g_al1[(r + 8) * 4 + hh] = alp1; g_ar1[(r + 8) * 4 + hh] = arp1; }
        }
    }
}

// ---------------- single-sweep fused softmax + aggregation layer1 (fp16 gathers) ----------------
__global__ void k_agg1(const float* __restrict__ b1, int n) {
    __shared__ float sw[8][32][4];
    __shared__ int   sr[8][32];
    int w = (blockIdx.x * blockDim.x + threadIdx.x) >> 5;
    if (w >= n) return;
    int lane = threadIdx.x & 31;
    int wz = (threadIdx.x >> 5) & 7;
    int c = w;
    float dc = g_dinv[c];
    float4 alc = *(const float4*)&g_al1[c * 4];
    float4 arc = *(const float4*)&g_ar1[c * 4];
    int beg = g_off[c], end = g_off[c + 1];
    int h = lane >> 3;

    float4 ps = make_float4(0.f, 0.f, 0.f, 0.f);
    float4 acc = make_float4(0.f, 0.f, 0.f, 0.f);

    for (int t0 = beg; t0 < end; t0 += 32) {
        int j = t0 + lane;
        if (j < end) {
            int r = __ldg(&g_adj[j]);
            float4 ar4 = *(const float4*)&g_ar1[r * 4];
            float di = g_dinv[r];
            float e0 = __expf(lrelu(alc.x + ar4.x));
            float e1 = __expf(lrelu(alc.y + ar4.y));
            float e2 = __expf(lrelu(alc.z + ar4.z));
            float e3 = __expf(lrelu(alc.w + ar4.w));
            ps.x += e0; ps.y += e1; ps.z += e2; ps.w += e3;
            sw[wz][lane][0] = di * e0;
            sw[wz][lane][1] = di * e1;
            sw[wz][lane][2] = di * e2;
            sw[wz][lane][3] = di * e3;
            sr[wz][lane] = r;
        }
        __syncwarp();
        int cnt = min(32, end - t0);
#pragma unroll 4
        for (int u = 0; u < cnt; u++) {
            int r = sr[wz][u];
            float wh = sw[wz][u][h];
            uint2 u2 = *(const uint2*)&g_xt1[(size_t)r * 128 + lane * 4];
            float2 f0 = __half22float2(*(__half2*)&u2.x);
            float2 f1 = __half22float2(*(__half2*)&u2.y);
            acc.x += wh * f0.x; acc.y += wh * f0.y;
            acc.z += wh * f1.x; acc.w += wh * f1.y;
        }
        __syncwarp();
    }

#pragma unroll
    for (int d = 16; d > 0; d >>= 1) {
        ps.x += __shfl_xor_sync(0xffffffffu, ps.x, d);
        ps.y += __shfl_xor_sync(0xffffffffu, ps.y, d);
        ps.z += __shfl_xor_sync(0xffffffffu, ps.z, d);
        ps.w += __shfl_xor_sync(0xffffffffu, ps.w, d);
    }
    float se0 = __expf(lrelu(alc.x + arc.x));
    float se1 = __expf(lrelu(alc.y + arc.y));
    float se2 = __expf(lrelu(alc.z + arc.z));
    float se3 = __expf(lrelu(alc.w + arc.w));
    float rs0 = __fdividef(1.0f, ps.x + se0 + 1e-16f);
    float rs1 = __fdividef(1.0f, ps.y + se1 + 1e-16f);
    float rs2 = __fdividef(1.0f, ps.z + se2 + 1e-16f);
    float rs3 = __fdividef(1.0f, ps.w + se3 + 1e-16f);
    float seh = h < 2 ? (h == 0 ? se0 : se1) : (h == 2 ? se2 : se3);
    float rsh = h < 2 ? (h == 0 ? rs0 : rs1) : (h == 2 ? rs2 : rs3);

    uint2 uc = *(const uint2*)&g_xt1[(size_t)c * 128 + lane * 4];
    float2 c0 = __half22float2(*(__half2*)&uc.x);
    float2 c1 = __half22float2(*(__half2*)&uc.y);
    float wself = dc * seh;
    acc.x += wself * c0.x; acc.y += wself * c0.y;
    acc.z += wself * c1.x; acc.w += wself * c1.y;
    float sc = dc * rsh;

    float4 b = *(const float4*)&b1[lane * 4];
    float ox = fmaxf(acc.x * sc + b.x, 0.f);
    float oy = fmaxf(acc.y * sc + b.y, 0.f);
    float oz = fmaxf(acc.z * sc + b.z, 0.f);
    float ow = fmaxf(acc.w * sc + b.w, 0.f);
    uint2 st;
    *(__half2*)&st.x = __floats2half2_rn(ox, oy);
    *(__half2*)&st.y = __floats2half2_rn(oz, ow);
    *(uint2*)&g_h1[(size_t)c * 128 + lane * 4] = st;
}

// ---------------- GEMM2 (tf32, fp16 in) + fused alar2 epilogue, fp16 xt2 out ----------------
__global__ __launch_bounds__(256, 2) void k_gemm2(const float* __restrict__ W2,
                                                  const float* __restrict__ att, int n) {
    __shared__ float Hs[32][132];
    __shared__ float Ws2[32][20];
    int tid = threadIdx.x, lane = tid & 31, wid = tid >> 5;
    int m0 = blockIdx.x * 128;
    int wm = wid * 16;

    float acc[2][4];
#pragma unroll
    for (int nt = 0; nt < 2; nt++)
#pragma unroll
        for (int q = 0; q < 4; q++) acc[nt][q] = 0.f;

    int lm = tid & 127;
    int lkq = (tid >> 7) * 16;
    int wkk = tid >> 3, wc = (tid & 7) * 2;

    for (int k0 = 0; k0 < 128; k0 += 32) {
        uint4 hv0 = make_uint4(0, 0, 0, 0), hv1 = hv0;
        if (m0 + lm < n) {
            const __half* hp = &g_h1[(size_t)(m0 + lm) * 128 + k0 + lkq];
            hv0 = *(const uint4*)hp;
            hv1 = *(const uint4*)(hp + 8);
        }
        {
            const uint32_t* hu = &hv0.x;
#pragma unroll
            for (int j = 0; j < 4; j++) {
                float2 f = __half22float2(*(__half2*)&hu[j]);
                Hs[lkq + j * 2 + 0][lm] = f.x;
                Hs[lkq + j * 2 + 1][lm] = f.y;
            }
            const uint32_t* hu2 = &hv1.x;
#pragma unroll
            for (int j = 0; j < 4; j++) {
                float2 f = __half22float2(*(__half2*)&hu2[j]);
                Hs[lkq + 8 + j * 2 + 0][lm] = f.x;
                Hs[lkq + 8 + j * 2 + 1][lm] = f.y;
            }
        }
        Ws2[wkk][wc]     = f2tf(W2[(size_t)(k0 + wkk) * 16 + wc]);
        Ws2[wkk][wc + 1] = f2tf(W2[(size_t)(k0 + wkk) * 16 + wc + 1]);
        __syncthreads();

#pragma unroll
        for (int kk = 0; kk < 32; kk += 8) {
            int ar = lane >> 2, ak = kk + (lane & 3);
            uint32_t a[4];
            a[0] = __float_as_uint(Hs[ak][wm + ar]);
            a[1] = __float_as_uint(Hs[ak][wm + ar + 8]);
            a[2] = __float_as_uint(Hs[ak + 4][wm + ar]);
            a[3] = __float_as_uint(Hs[ak + 4][wm + ar + 8]);
            uint32_t b0[2], b1[2];
            b0[0] = __float_as_uint(Ws2[ak][ar]);
            b0[1] = __float_as_uint(Ws2[ak + 4][ar]);
            b1[0] = __float_as_uint(Ws2[ak][8 + ar]);
            b1[1] = __float_as_uint(Ws2[ak + 4][8 + ar]);
            mma_tf32(acc[0], a, b0);
            mma_tf32(acc[1], a, b1);
        }
        __syncthreads();
    }

    int ar = lane >> 2, ac = (lane & 3) * 2;
#pragma unroll
    for (int nt = 0; nt < 2; nt++) {
        int r = m0 + wm + ar;
        int c = nt * 8 + ac;
        if (r < n)
            *(__half2*)&g_xt2[(size_t)r * 16 + c] = __floats2half2_rn(acc[nt][0], acc[nt][1]);
        if (r + 8 < n)
            *(__half2*)&g_xt2[(size_t)(r + 8) * 16 + c] = __floats2half2_rn(acc[nt][2], acc[nt][3]);
    }

    // ---- fused alar2 epilogue ----
    float wlv[4], wrv[4];
#pragma unroll
    for (int nt = 0; nt < 2; nt++) {
        int cc = nt * 8 + ac;
        wlv[nt * 2 + 0] = att[cc];
        wlv[nt * 2 + 1] = att[cc + 1];
        wrv[nt * 2 + 0] = att[16 + cc];
        wrv[nt * 2 + 1] = att[16 + cc + 1];
    }
    float alp0 = 0.f, arp0 = 0.f, alp1 = 0.f, arp1 = 0.f;
#pragma unroll
    for (int nt = 0; nt < 2; nt++) {
        alp0 += acc[nt][0] * wlv[nt * 2] + acc[nt][1] * wlv[nt * 2 + 1];
        arp0 += acc[nt][0] * wrv[nt * 2] + acc[nt][1] * wrv[nt * 2 + 1];
        alp1 += acc[nt][2] * wlv[nt * 2] + acc[nt][3] * wlv[nt * 2 + 1];
        arp1 += acc[nt][2] * wrv[nt * 2] + acc[nt][3] * wrv[nt * 2 + 1];
    }
#pragma unroll
    for (int d = 1; d <= 2; d <<= 1) {
        alp0 += __shfl_xor_sync(0xffffffffu, alp0, d);
        arp0 += __shfl_xor_sync(0xffffffffu, arp0, d);
        alp1 += __shfl_xor_sync(0xffffffffu, alp1, d);
        arp1 += __shfl_xor_sync(0xffffffffu, arp1, d);
    }
    if ((lane & 3) == 0) {
        int r = m0 + wm + ar;
        if (r < n)     { g_al2[r] = alp0;     g_ar2[r] = arp0; }
        if (r + 8 < n) { g_al2[r + 8] = alp1; g_ar2[r + 8] = arp1; }
    }
}

// ---------------- layer2 agg: half-warp per node, shfl staging ----------------
__global__ void k_agg2(const float* __restrict__ b2, int n, float* __restrict__ out) {
    int hw = (blockIdx.x * blockDim.x + threadIdx.x) >> 4;   // half-warp = node
    int sub = threadIdx.x & 15;
    unsigned hm = 0xFFFFu << (threadIdx.x & 16);
    bool valid = hw < n;
    int c = valid ? hw : (n - 1);
    float dc = g_dinv[c];
    float alc = g_al2[c];
    int beg = g_off[c], end = g_off[c + 1];

    float ps = 0.f, acc = 0.f;
    for (int t0 = beg; t0 < end; t0 += 16) {
        int j = t0 + sub;
        int r = 0; float wv = 0.f;
        if (j < end) {
            r = __ldg(&g_adj[j]);
            float e = __expf(lrelu(alc + g_ar2[r]));
            ps += e;
            wv = g_dinv[r] * e;
        }
        int cnt = min(16, end - t0);
        for (int u = 0; u < cnt; u++) {
            int ru = __shfl_sync(hm, r, u, 16);
            float wu = __shfl_sync(hm, wv, u, 16);
            acc += wu * __half2float(g_xt2[(size_t)ru * 16 + sub]);
        }
    }
#pragma unroll
    for (int d = 8; d > 0; d >>= 1)
        ps += __shfl_xor_sync(hm, ps, d, 16);
    float se = __expf(lrelu(alc + g_ar2[c]));
    float rs = __fdividef(1.0f, ps + se + 1e-16f);
    acc += dc * se * __half2float(g_xt2[(size_t)c * 16 + sub]);
    if (valid) out[(size_t)c * 16 + sub] = dc * rs * acc + b2[sub];
}

// ---------------- launch (stream-forked: CSR build overlaps GEMM1) ----------------
extern "C" void kernel_launch(void* const* d_in, const int* in_sizes, int n_in,
                              void* d_out, int out_size) {
    const float* x    = (const float*)d_in[0];
    const int*   ei   = (const int*)d_in[1];
    const float* W1   = (const float*)d_in[2];
    const float* att1 = (const float*)d_in[3];
    const float* b1   = (const float*)d_in[4];
    const float* W2   = (const float*)d_in[5];
    const float* att2 = (const float*)d_in[6];
    const float* b2   = (const float*)d_in[7];
    float* out = (float*)d_out;

    int n = in_sizes[0] / 256;
    int e = in_sizes[1] / 2;
    int nb = (n + 1023) / 1024;
    const int T = 256;

    // kernel_launch is invoked only for the correctness run and the capture
    // call, so creating a side stream + events here (and leaking them) is
    // cheap and keeps the function stateless across calls.
    cudaStream_t s2;
    cudaEvent_t evFork, evJoin;
    cudaStreamCreateWithFlags(&s2, cudaStreamNonBlocking);
    cudaEventCreateWithFlags(&evFork, cudaEventDisableTiming);
    cudaEventCreateWithFlags(&evJoin, cudaEventDisableTiming);

    // fork: side stream builds the CSR while the main stream runs GEMM1
    cudaEventRecord(evFork, 0);
    cudaStreamWaitEvent(s2, evFork, 0);

    // chain A (side stream): degree + CSR build
    k_init<<<(n + T - 1) / T, T, 0, s2>>>(n);
    k_deg_count<<<(e + T - 1) / T, T, 0, s2>>>(ei, e);
    k_scan_blocks<<<nb, 1024, 0, s2>>>(n);
    k_scan_add<<<nb, 1024, 0, s2>>>(n, e);
    k_scatter<<<(e + T - 1) / T, T, 0, s2>>>(ei, e);
    cudaEventRecord(evJoin, s2);

    // chain B (main stream): feature transform
    k_gemm1<<<(n + 127) / 128, 256>>>(x, W1, att1, n);

    // join: aggregation needs both chains
    cudaStreamWaitEvent(0, evJoin, 0);
    k_agg1<<<(n * 32 + 255) / 256, 256>>>(b1, n);

    k_gemm2<<<(n + 127) / 128, 256>>>(W2, att2, n);
    k_agg2<<<(n * 16 + 255) / 256, 256>>>(b2, n, out);
}